// round 14
// baseline (speedup 1.0000x reference)
#include <cuda_runtime.h>
#include <cuda_fp16.h>
#include <mma.h>
#include <cstdint>
#include <cstddef>

using namespace nvcuda;

// Problem constants: N=100000, E=1600000, F=128, H=64, C=40, G=2048
#define NMAX 100000
#define EMAX 1600000
#define GMAX 2048

// ---------------- scratch (device globals; no runtime alloc allowed) ----------------
__device__ __align__(128) __half g_hws [NMAX * 64];  // layer-1 (h@W1c)*isq (fp16)
__device__ __align__(128) __half g_hws2[NMAX * 64];  // layer-2 (h1@W2c)*isq (fp16)
__device__ __align__(128) __half g_h1  [NMAX * 64];  // layer-1 activations (fp16)
__device__ __align__(16)  float  g_deg[NMAX];        // isq
__device__ __align__(128) float  g_readout[GMAX * 64];
__device__ __align__(16)  int    g_cnt[NMAX];        // per-dst degree
__device__ __align__(16)  int    g_ptr[NMAX];        // CSR row starts
__device__ __align__(16)  int    g_cursor[NMAX];     // fill cursors
__device__ __align__(16)  int    g_csr_src[EMAX];    // CSR column (src) indices
__device__ int g_scanflag[128];                      // lookback published aggregates (+1)
__device__ int g_idx32;                              // 1 if indices are int32

// ---------------- per-block index-dtype detection ----------------
__device__ __forceinline__ int block_detect_idx32(const void* e, int E, long long nlim,
                                                  int* s_flag) {
    if (threadIdx.x == 0) *s_flag = 0;
    __syncthreads();
    int m = E < 64 ? E : 64;
    if ((int)threadIdx.x < m) {
        long long v = ((const long long*)e)[threadIdx.x];
        if (v < 0 || v >= nlim) *s_flag = 1;
    }
    __syncthreads();
    return *s_flag;
}

// ---------------- degree histogram ----------------
__global__ void __launch_bounds__(256) k_hist(const void* __restrict__ eidx, int E,
                                              long long nlim) {
    __shared__ int sf;
    int idx32 = block_detect_idx32(eidx, E, nlim, &sf);
    if (blockIdx.x == 0 && threadIdx.x == 0) g_idx32 = idx32;
    int base = (blockIdx.x * blockDim.x + threadIdx.x) * 4;
    if (idx32) {
        const int* d = (const int*)eidx + E;
#pragma unroll
        for (int k = 0; k < 4; k++) {
            int e = base + k;
            if (e < E) atomicAdd(&g_cnt[d[e]], 1);
        }
    } else {
        const long long* d = (const long long*)eidx + E;
#pragma unroll
        for (int k = 0; k < 4; k++) {
            int e = base + k;
            if (e < E) atomicAdd(&g_cnt[(int)d[e]], 1);
        }
    }
}

// ---------------- single-pass exclusive scan (lookback) + cursor + isq ----------------
__global__ void __launch_bounds__(256) k_scan(int n) {
    __shared__ int wsum[8];
    __shared__ int red[8];
    __shared__ int s_prefix;
    int bid = blockIdx.x;
    int base = bid * 1024 + threadIdx.x * 4;

    int c0 = 0, c1 = 0, c2 = 0, c3 = 0;
    if (base + 3 < n) {
        int4 c = *(const int4*)&g_cnt[base];
        c0 = c.x; c1 = c.y; c2 = c.z; c3 = c.w;
    } else if (base < n) {
        c0 = g_cnt[base];
        if (base + 1 < n) c1 = g_cnt[base + 1];
        if (base + 2 < n) c2 = g_cnt[base + 2];
    }
    int tot = c0 + c1 + c2 + c3;
    int lane = threadIdx.x & 31, wid = threadIdx.x >> 5;
    int v = tot;
#pragma unroll
    for (int o = 1; o < 32; o <<= 1) {
        int u = __shfl_up_sync(0xffffffffu, v, o);
        if (lane >= o) v += u;
    }
    if (lane == 31) wsum[wid] = v;
    __syncthreads();
    if (threadIdx.x == 0) {
        int s = 0;
        for (int i = 0; i < 8; i++) { int t = wsum[i]; wsum[i] = s; s += t; }
        atomicExch(&g_scanflag[bid], s + 1);
    }
    __syncthreads();

    int part = 0;
    if ((int)threadIdx.x < bid) {
        volatile int* f = &g_scanflag[threadIdx.x];
        int x;
        do { x = *f; } while (x == 0);
        part = x - 1;
    }
#pragma unroll
    for (int o = 16; o; o >>= 1) part += __shfl_xor_sync(0xffffffffu, part, o);
    if (lane == 0) red[wid] = part;
    __syncthreads();
    if (threadIdx.x == 0) {
        int s = 0;
        for (int i = 0; i < 8; i++) s += red[i];
        s_prefix = s;
    }
    __syncthreads();

    int excl = v - tot + wsum[wid] + s_prefix;
    if (base < n) {
        int p0 = excl, p1 = p0 + c0, p2 = p1 + c1, p3 = p2 + c2;
        g_ptr[base] = p0; g_cursor[base] = p0; g_deg[base] = rsqrtf((float)c0 + 1.0f);
        if (base + 1 < n) { g_ptr[base+1] = p1; g_cursor[base+1] = p1; g_deg[base+1] = rsqrtf((float)c1 + 1.0f); }
        if (base + 2 < n) { g_ptr[base+2] = p2; g_cursor[base+2] = p2; g_deg[base+2] = rsqrtf((float)c2 + 1.0f); }
        if (base + 3 < n) { g_ptr[base+3] = p3; g_cursor[base+3] = p3; g_deg[base+3] = rsqrtf((float)c3 + 1.0f); }
    }
}

// ---------------- CSR fill ----------------
__global__ void __launch_bounds__(256) k_fill(const void* __restrict__ eidx, int E,
                                              long long nlim) {
    __shared__ int sf;
    int idx32 = block_detect_idx32(eidx, E, nlim, &sf);
    int base = (blockIdx.x * blockDim.x + threadIdx.x) * 4;
#pragma unroll
    for (int k = 0; k < 4; k++) {
        int e = base + k;
        if (e >= E) break;
        int src, dst;
        if (idx32) {
            const int* p = (const int*)eidx;
            src = p[e]; dst = p[E + e];
        } else {
            const long long* p = (const long long*)eidx;
            src = (int)p[e]; dst = (int)p[E + e];
        }
        int pos = atomicAdd(&g_cursor[dst], 1);
        g_csr_src[pos] = src;
    }
}

// ---------------- fused pre-MLP + layer-1 GEMM: hws = ((x@W1+b1)@W2)*isq -------------
// 46080B static SMEM: W1s[0,18432) W2s[18432,27648) As[27648,46080); C1 aliases W1s
// (dead after phase 1; guarded by 2nd block barrier). launch_bounds(256,4).
__global__ void __launch_bounds__(256, 4) k_gemm0(const float* __restrict__ x,
                                                  const float* __restrict__ W1,
                                                  const float* __restrict__ b1,
                                                  const float* __restrict__ W2,
                                                  const int* __restrict__ cnt,
                                                  __half* __restrict__ out, int n) {
    __shared__ __align__(16) char sm[46080];
    __half* W1s = (__half*)sm;                       // 128 x 64, ld 72
    __half* W2s = (__half*)(sm + 18432);             // 64 x 64, ld 72
    __half* As  = (__half*)(sm + 27648);             // 128 x 64, ld 72 (warp strips)
    __half* C1  = W1s;                               // aliased after barrier #2

    int tid = threadIdx.x;
    int warpId = tid >> 5, lane = tid & 31;
    int nodeBase = blockIdx.x * 128;

    for (int i = tid; i < 128 * 64; i += 256) {
        int r = i >> 6, c = i & 63;
        W1s[r * 72 + c] = __float2half(W1[i]);
    }
    for (int i = tid; i < 64 * 64; i += 256) {
        int r = i >> 6, c = i & 63;
        W2s[r * 72 + c] = __float2half(W2[i]);
    }
    __syncthreads();   // barrier #1: W staged

    __half* Aw   = As + warpId * 1152;   // warp strip: 16 x 72 halfs
    __half* C1w  = C1 + warpId * 1152;
    float*  tmpf = (float*)Aw;           // 16 x 20 fp32 alias (A dead when used)

    int srow = tid >> 1;
    int wrow = srow & 15;
    int scol = (tid & 1) * 32;
    int sgn = nodeBase + srow;
    bool sok = (sgn < n);
    const float* aptr = x + (size_t)sgn * 128 + scol;

    // ---- phase 1: C = x @ W1 (K=128, two 64-col chunks), warp-local ----
    wmma::fragment<wmma::accumulator, 16, 16, 16, float> cf[4];
#pragma unroll
    for (int t = 0; t < 4; t++) wmma::fill_fragment(cf[t], 0.0f);

#pragma unroll
    for (int c = 0; c < 2; c++) {
        __syncwarp();
#pragma unroll
        for (int q = 0; q < 4; q++) {
            float4 f0, f1;
            if (sok) {
                f0 = *(const float4*)(aptr + c * 64 + q * 8);
                f1 = *(const float4*)(aptr + c * 64 + q * 8 + 4);
            } else {
                f0 = make_float4(0.f, 0.f, 0.f, 0.f);
                f1 = f0;
            }
            __align__(16) __half2 hs[4];
            hs[0] = __floats2half2_rn(f0.x, f0.y);
            hs[1] = __floats2half2_rn(f0.z, f0.w);
            hs[2] = __floats2half2_rn(f1.x, f1.y);
            hs[3] = __floats2half2_rn(f1.z, f1.w);
            *(uint4*)(Aw + wrow * 72 + scol + q * 8) = *(const uint4*)hs;
        }
        __syncwarp();
#pragma unroll
        for (int kk = 0; kk < 64; kk += 16) {
            wmma::fragment<wmma::matrix_a, 16, 16, 16, __half, wmma::row_major> af;
            wmma::load_matrix_sync(af, Aw + kk, 72);
#pragma unroll
            for (int t = 0; t < 4; t++) {
                wmma::fragment<wmma::matrix_b, 16, 16, 16, __half, wmma::row_major> bf;
                wmma::load_matrix_sync(bf, W1s + (c * 64 + kk) * 72 + t * 16, 72);
                wmma::mma_sync(cf[t], af, bf, cf[t]);
            }
        }
    }
    __syncthreads();   // barrier #2: all warps done reading W1s -> C1 may overwrite it

    // ---- phase 2: cf -> (+b1) -> fp16 C1 (aliased over W1s), warp-local ----
    int tr = lane >> 1;
    int tc = (lane & 1) * 8;
#pragma unroll
    for (int t = 0; t < 4; t++) {
        __syncwarp();
        wmma::store_matrix_sync(tmpf, cf[t], 20, wmma::mem_row_major);
        __syncwarp();
        const float* s = tmpf + tr * 20 + tc;
        float4 v0 = *(const float4*)s;
        float4 v1 = *(const float4*)(s + 4);
        float4 ba = *(const float4*)(b1 + t * 16 + tc);
        float4 bb = *(const float4*)(b1 + t * 16 + tc + 4);
        __align__(16) __half2 hs[4];
        hs[0] = __floats2half2_rn(v0.x + ba.x, v0.y + ba.y);
        hs[1] = __floats2half2_rn(v0.z + ba.z, v0.w + ba.w);
        hs[2] = __floats2half2_rn(v1.x + bb.x, v1.y + bb.y);
        hs[3] = __floats2half2_rn(v1.z + bb.z, v1.w + bb.w);
        __syncwarp();
        *(uint4*)(C1w + tr * 72 + t * 16 + tc) = *(const uint4*)hs;
    }
    __syncwarp();

    // ---- phase 3: D = C1 @ W2 (K=64), warp-local ----
    wmma::fragment<wmma::accumulator, 16, 16, 16, float> cg[4];
#pragma unroll
    for (int t = 0; t < 4; t++) wmma::fill_fragment(cg[t], 0.0f);
#pragma unroll
    for (int kk = 0; kk < 64; kk += 16) {
        wmma::fragment<wmma::matrix_a, 16, 16, 16, __half, wmma::row_major> af;
        wmma::load_matrix_sync(af, C1w + kk, 72);
#pragma unroll
        for (int t = 0; t < 4; t++) {
            wmma::fragment<wmma::matrix_b, 16, 16, 16, __half, wmma::row_major> bf;
            wmma::load_matrix_sync(bf, W2s + kk * 72 + t * 16, 72);
            wmma::mma_sync(cg[t], af, bf, cg[t]);
        }
    }

    // ---- epilogue: *isq, fp16 out ----
    int gn = nodeBase + warpId * 16 + tr;
    float siq = (gn < n) ? rsqrtf((float)__ldg(&cnt[gn]) + 1.0f) : 0.f;
#pragma unroll
    for (int t = 0; t < 4; t++) {
        __syncwarp();
        wmma::store_matrix_sync(tmpf, cg[t], 20, wmma::mem_row_major);
        __syncwarp();
        if (gn < n) {
            const float* s = tmpf + tr * 20 + tc;
            float4 v0 = *(const float4*)s;
            float4 v1 = *(const float4*)(s + 4);
            __align__(16) __half2 p[4];
            p[0] = __floats2half2_rn(v0.x * siq, v0.y * siq);
            p[1] = __floats2half2_rn(v0.z * siq, v0.w * siq);
            p[2] = __floats2half2_rn(v1.x * siq, v1.y * siq);
            p[3] = __floats2half2_rn(v1.z * siq, v1.w * siq);
            *(uint4*)(out + (size_t)gn * 64 + t * 16 + tc) = *(const uint4*)p;
        }
    }
}

// ---------------- fused gather1 + LN + ReLU + layer-2 GEMM -----------------------------
// Block = 256 thr / 8 warps / 128 nodes. Each warp gathers its own 16 nodes (4 per
// 8-lane group, warp-max predicated loop), writes h1 rows to its OWN SMEM strip
// (+ write-through to g_h1 for the skip), then runs the K=64 WMMA from that strip.
// Output hws2 = (h1 @ W)*isq -> g_hws2 (separate buffer: g_hws still being read).
__global__ void __launch_bounds__(256, 4) k_gather_gemm(const float* __restrict__ bias,
                                                        const float* __restrict__ lng,
                                                        const float* __restrict__ lnb,
                                                        const float* __restrict__ W,
                                                        const int* __restrict__ cnt,
                                                        __half* __restrict__ h1out,
                                                        __half* __restrict__ out, int n) {
    const unsigned FULL = 0xffffffffu;
    __shared__ __align__(16) __half Ws[64 * 72];     // 9216B
    __shared__ __align__(16) __half Hs[128 * 72];    // 18432B

    int tid = threadIdx.x;
    int warpId = tid >> 5, lane = tid & 31;
    int grp = lane >> 3, sub = lane & 7;
    int nodeBase = blockIdx.x * 128;

    for (int i = tid; i < 64 * 64; i += 256) {
        int r = i >> 6, c = i & 63;
        Ws[r * 72 + c] = __float2half(W[i]);
    }
    __syncthreads();   // only block barrier

    __half* Hw = Hs + warpId * 1152;

    // preload per-lane params (reused for all 4 nodes)
    const float4* b4 = (const float4*)bias;
    float4 bl = __ldg(&b4[sub * 2]), bh = __ldg(&b4[sub * 2 + 1]);
    float bb[8] = {bl.x, bl.y, bl.z, bl.w, bh.x, bh.y, bh.z, bh.w};
    const float4* g4 = (const float4*)lng;
    const float4* l4 = (const float4*)lnb;
    float4 gl = __ldg(&g4[sub * 2]), gh = __ldg(&g4[sub * 2 + 1]);
    float4 ll = __ldg(&l4[sub * 2]), lh = __ldg(&l4[sub * 2 + 1]);
    float gg[8] = {gl.x, gl.y, gl.z, gl.w, gh.x, gh.y, gh.z, gh.w};
    float lb[8] = {ll.x, ll.y, ll.z, ll.w, lh.x, lh.y, lh.z, lh.w};

    const uint4* hw4 = (const uint4*)g_hws;

#pragma unroll
    for (int it = 0; it < 4; it++) {
        int localRow = warpId * 16 + grp * 4 + it;
        int node = nodeBase + localRow;
        bool ok = (node < n);
        int nodec = ok ? node : (n - 1);
        int start = g_ptr[nodec];
        int cntv  = ok ? g_cnt[nodec] : 0;

        int mmax = cntv;
        mmax = max(mmax, __shfl_xor_sync(FULL, mmax, 8));
        mmax = max(mmax, __shfl_xor_sync(FULL, mmax, 16));

        __half2 acc[4];
        __half2 z = __float2half2_rn(0.f);
#pragma unroll
        for (int k = 0; k < 4; k++) acc[k] = z;

        for (int done = 0; done < mmax; done += 8) {
            int b = 0;
            if (done + sub < cntv) b = __ldg(&g_csr_src[start + done + sub]);
            int lim = cntv - done;
            uint4 v[8];
#pragma unroll
            for (int j = 0; j < 8; j++) {
                int s = __shfl_sync(FULL, b, (grp << 3) + j);
                v[j] = make_uint4(0u, 0u, 0u, 0u);
                if (j < lim) v[j] = __ldg(&hw4[(size_t)s * 8 + sub]);
            }
#pragma unroll
            for (int j = 0; j < 8; j++) {
                const __half2* p = (const __half2*)&v[j];
                acc[0] = __hadd2(acc[0], p[0]);
                acc[1] = __hadd2(acc[1], p[1]);
                acc[2] = __hadd2(acc[2], p[2]);
                acc[3] = __hadd2(acc[3], p[3]);
            }
        }

        uint4 sv = __ldg(&hw4[(size_t)nodec * 8 + sub]);
        const __half2* ps = (const __half2*)&sv;
        float isqn = g_deg[nodec];

        float v8[8];
#pragma unroll
        for (int k = 0; k < 4; k++) {
            float2 f  = __half22float2(acc[k]);
            float2 fs = __half22float2(ps[k]);
            v8[2 * k]     = fmaf(isqn, f.x + fs.x, bb[2 * k]);
            v8[2 * k + 1] = fmaf(isqn, f.y + fs.y, bb[2 * k + 1]);
        }

        float sum = 0.f;
#pragma unroll
        for (int i = 0; i < 8; i++) sum += v8[i];
#pragma unroll
        for (int o = 4; o; o >>= 1) sum += __shfl_xor_sync(FULL, sum, o);
        float mu = sum * (1.0f / 64.0f);

        float var = 0.f, d8[8];
#pragma unroll
        for (int i = 0; i < 8; i++) { d8[i] = v8[i] - mu; var += d8[i] * d8[i]; }
#pragma unroll
        for (int o = 4; o; o >>= 1) var += __shfl_xor_sync(FULL, var, o);
        float rstd = rsqrtf(var * (1.0f / 64.0f) + 1e-5f);

        __align__(16) __half2 p[4];
#pragma unroll
        for (int k = 0; k < 4; k++) {
            float a = fmaxf(fmaf(d8[2*k]   * rstd, gg[2*k],   lb[2*k]),   0.f);
            float c = fmaxf(fmaf(d8[2*k+1] * rstd, gg[2*k+1], lb[2*k+1]), 0.f);
            p[k] = __floats2half2_rn(a, c);
        }
        // SMEM strip row (always) + global h1 write-through (real nodes)
        *(uint4*)(Hw + (grp * 4 + it) * 72 + sub * 8) = *(const uint4*)p;
        if (ok) *(uint4*)(h1out + (size_t)node * 64 + sub * 8) = *(const uint4*)p;
    }
    __syncwarp();

    // ---- layer-2 WMMA from own strip ----
    wmma::fragment<wmma::accumulator, 16, 16, 16, float> cf[4];
#pragma unroll
    for (int t = 0; t < 4; t++) wmma::fill_fragment(cf[t], 0.0f);
#pragma unroll
    for (int kk = 0; kk < 64; kk += 16) {
        wmma::fragment<wmma::matrix_a, 16, 16, 16, __half, wmma::row_major> af;
        wmma::load_matrix_sync(af, Hw + kk, 72);
#pragma unroll
        for (int t = 0; t < 4; t++) {
            wmma::fragment<wmma::matrix_b, 16, 16, 16, __half, wmma::row_major> bf;
            wmma::load_matrix_sync(bf, Ws + kk * 72 + t * 16, 72);
            wmma::mma_sync(cf[t], af, bf, cf[t]);
        }
    }

    float* tmpf = (float*)Hw;          // strip dead after fragment loads
    int tr = lane >> 1;
    int tc = (lane & 1) * 8;
    int gn = nodeBase + warpId * 16 + tr;
    float siq = (gn < n) ? rsqrtf((float)__ldg(&cnt[gn]) + 1.0f) : 0.f;
#pragma unroll
    for (int t = 0; t < 4; t++) {
        __syncwarp();
        wmma::store_matrix_sync(tmpf, cf[t], 20, wmma::mem_row_major);
        __syncwarp();
        if (gn < n) {
            const float* s = tmpf + tr * 20 + tc;
            float4 v0 = *(const float4*)s;
            float4 v1 = *(const float4*)(s + 4);
            __align__(16) __half2 p[4];
            p[0] = __floats2half2_rn(v0.x * siq, v0.y * siq);
            p[1] = __floats2half2_rn(v0.z * siq, v0.w * siq);
            p[2] = __floats2half2_rn(v1.x * siq, v1.y * siq);
            p[3] = __floats2half2_rn(v1.z * siq, v1.w * siq);
            *(uint4*)(out + (size_t)gn * 64 + t * 16 + tc) = *(const uint4*)p;
        }
    }
}

// ---------------- gather2: + self + bias + LN + ReLU + skip + readout ----------------
__global__ void __launch_bounds__(256) k_gather(const __half* __restrict__ hws,
                                                const float* __restrict__ bias,
                                                const float* __restrict__ lng,
                                                const float* __restrict__ lnb,
                                                int n, const void* __restrict__ batch) {
    const unsigned FULL = 0xffffffffu;
    int t = blockIdx.x * blockDim.x + threadIdx.x;
    int node = t >> 3;
    int lane = threadIdx.x & 31;
    int grp = lane >> 3, sub = lane & 7;
    bool ok = (node < n);
    int nodec = ok ? node : (n - 1);

    int start = g_ptr[nodec];
    int cnt   = ok ? g_cnt[nodec] : 0;

    int mmax = cnt;
    mmax = max(mmax, __shfl_xor_sync(FULL, mmax, 8));
    mmax = max(mmax, __shfl_xor_sync(FULL, mmax, 16));

    const uint4* hw4 = (const uint4*)hws;
    __half2 acc[4];
    __half2 z = __float2half2_rn(0.f);
#pragma unroll
    for (int k = 0; k < 4; k++) acc[k] = z;

    for (int done = 0; done < mmax; done += 8) {
        int b = 0;
        if (done + sub < cnt) b = __ldg(&g_csr_src[start + done + sub]);
        int lim = cnt - done;
        uint4 v[8];
#pragma unroll
        for (int j = 0; j < 8; j++) {
            int s = __shfl_sync(FULL, b, (grp << 3) + j);
            v[j] = make_uint4(0u, 0u, 0u, 0u);
            if (j < lim) v[j] = __ldg(&hw4[(size_t)s * 8 + sub]);
        }
#pragma unroll
        for (int j = 0; j < 8; j++) {
            const __half2* p = (const __half2*)&v[j];
            acc[0] = __hadd2(acc[0], p[0]);
            acc[1] = __hadd2(acc[1], p[1]);
            acc[2] = __hadd2(acc[2], p[2]);
            acc[3] = __hadd2(acc[3], p[3]);
        }
    }

    uint4 sv = __ldg(&hw4[(size_t)nodec * 8 + sub]);
    const __half2* ps = (const __half2*)&sv;
    float isqn = g_deg[nodec];
    const float4* b4 = (const float4*)bias;
    float4 bl = __ldg(&b4[sub * 2]), bh = __ldg(&b4[sub * 2 + 1]);
    float bb[8] = {bl.x, bl.y, bl.z, bl.w, bh.x, bh.y, bh.z, bh.w};

    float v8[8];
#pragma unroll
    for (int k = 0; k < 4; k++) {
        float2 f  = __half22float2(acc[k]);
        float2 fs = __half22float2(ps[k]);
        v8[2 * k]     = fmaf(isqn, f.x + fs.x, bb[2 * k]);
        v8[2 * k + 1] = fmaf(isqn, f.y + fs.y, bb[2 * k + 1]);
    }

    float sum = 0.f;
#pragma unroll
    for (int i = 0; i < 8; i++) sum += v8[i];
#pragma unroll
    for (int o = 4; o; o >>= 1) sum += __shfl_xor_sync(FULL, sum, o);
    float mu = sum * (1.0f / 64.0f);

    float var = 0.f, d8[8];
#pragma unroll
    for (int i = 0; i < 8; i++) { d8[i] = v8[i] - mu; var += d8[i] * d8[i]; }
#pragma unroll
    for (int o = 4; o; o >>= 1) var += __shfl_xor_sync(FULL, var, o);
    float rstd = rsqrtf(var * (1.0f / 64.0f) + 1e-5f);

    const float4* g4 = (const float4*)lng;
    const float4* l4 = (const float4*)lnb;
    float4 gl = __ldg(&g4[sub * 2]), gh = __ldg(&g4[sub * 2 + 1]);
    float4 ll = __ldg(&l4[sub * 2]), lh = __ldg(&l4[sub * 2 + 1]);
    float gg[8] = {gl.x, gl.y, gl.z, gl.w, gh.x, gh.y, gh.z, gh.w};
    float lb[8] = {ll.x, ll.y, ll.z, ll.w, lh.x, lh.y, lh.z, lh.w};

    float o8[8];
#pragma unroll
    for (int i = 0; i < 8; i++)
        o8[i] = fmaxf(fmaf(d8[i] * rstd, gg[i], lb[i]), 0.f);

    if (!ok) return;
    uint4 hv = __ldg((const uint4*)(g_h1 + (size_t)node * 64 + sub * 8));
    const __half2* ph = (const __half2*)&hv;
    float h8[8];
#pragma unroll
    for (int k = 0; k < 4; k++) {
        float2 f = __half22float2(ph[k]);
        h8[2 * k] = f.x; h8[2 * k + 1] = f.y;
    }
    int grpi = g_idx32 ? ((const int*)batch)[node]
                       : (int)((const long long*)batch)[node];
    float4* r4 = (float4*)(g_readout + (size_t)grpi * 64 + sub * 8);
    atomicAdd(&r4[0], make_float4(o8[0] + h8[0], o8[1] + h8[1], o8[2] + h8[2], o8[3] + h8[3]));
    atomicAdd(&r4[1], make_float4(o8[4] + h8[4], o8[5] + h8[5], o8[6] + h8[6], o8[7] + h8[7]));
}

// ---------------- post GEMM ----------------
__global__ void k_post(const float* __restrict__ W, const float* __restrict__ b,
                       float* __restrict__ out, int G) {
    __shared__ float r[64];
    int g = blockIdx.x;
    r[threadIdx.x] = g_readout[(size_t)g * 64 + threadIdx.x];
    __syncthreads();
    int c = threadIdx.x;
    if (c < 40) {
        float acc = b[c];
#pragma unroll
        for (int k = 0; k < 64; k++) acc = fmaf(r[k], __ldg(&W[k * 40 + c]), acc);
        out[(size_t)g * 40 + c] = acc;
    }
}

// ---------------- launch ----------------
extern "C" void kernel_launch(void* const* d_in, const int* in_sizes, int n_in,
                              void* d_out, int out_size) {
    const float* x      = (const float*)d_in[0];
    const void*  eidx   = d_in[1];
    const void*  batch  = d_in[2];
    const float* pre_w  = (const float*)d_in[3];
    const float* pre_b  = (const float*)d_in[4];
    const float* c1_w   = (const float*)d_in[5];
    const float* c1_b   = (const float*)d_in[6];
    const float* n1_g   = (const float*)d_in[7];
    const float* n1_b   = (const float*)d_in[8];
    const float* c2_w   = (const float*)d_in[9];
    const float* c2_b   = (const float*)d_in[10];
    const float* n2_g   = (const float*)d_in[11];
    const float* n2_b   = (const float*)d_in[12];
    const float* post_w = (const float*)d_in[13];
    const float* post_b = (const float*)d_in[14];

    int N = in_sizes[0] / 128;
    int E = in_sizes[1] / 2;
    int G = out_size / 40;

    float* p_readout;
    __half *p_hws, *p_hws2, *p_h1;
    int *p_cnt, *p_flag;
    cudaGetSymbolAddress((void**)&p_hws,     g_hws);
    cudaGetSymbolAddress((void**)&p_hws2,    g_hws2);
    cudaGetSymbolAddress((void**)&p_h1,      g_h1);
    cudaGetSymbolAddress((void**)&p_cnt,     g_cnt);
    cudaGetSymbolAddress((void**)&p_flag,    g_scanflag);
    cudaGetSymbolAddress((void**)&p_readout, g_readout);

    static cudaStream_t s1 = nullptr, s2 = nullptr;
    static cudaEvent_t evFork = nullptr, evHist = nullptr, evG1 = nullptr, evCsr = nullptr;
    if (!s1) {
        cudaStreamCreateWithFlags(&s1, cudaStreamNonBlocking);
        cudaStreamCreateWithFlags(&s2, cudaStreamNonBlocking);
        cudaEventCreateWithFlags(&evFork, cudaEventDisableTiming);
        cudaEventCreateWithFlags(&evHist, cudaEventDisableTiming);
        cudaEventCreateWithFlags(&evG1,   cudaEventDisableTiming);
        cudaEventCreateWithFlags(&evCsr,  cudaEventDisableTiming);
    }

    cudaEventRecord(evFork, 0);
    cudaStreamWaitEvent(s1, evFork, 0);
    cudaStreamWaitEvent(s2, evFork, 0);

    // --- s2: memsets + CSR build ---
    cudaMemsetAsync(p_cnt, 0, (size_t)N * 4, s2);
    cudaMemsetAsync(p_flag, 0, 128 * 4, s2);
    cudaMemsetAsync(p_readout, 0, (size_t)G * 64 * 4, s2);
    k_hist<<<(E + 1023) / 1024, 256, 0, s2>>>(eidx, E, (long long)N);
    cudaEventRecord(evHist, s2);
    k_scan<<<(N + 1023) / 1024, 256, 0, s2>>>(N);
    k_fill<<<(E + 1023) / 1024, 256, 0, s2>>>(eidx, E, (long long)N);
    cudaEventRecord(evCsr, s2);

    // --- s1: fused pre-MLP + layer-1 GEMM (needs only hist counts) ---
    cudaStreamWaitEvent(s1, evHist, 0);
    k_gemm0<<<(N + 127) / 128, 256, 0, s1>>>(x, pre_w, pre_b, c1_w, p_cnt, p_hws, N);
    cudaEventRecord(evG1, s1);

    // --- join ---
    cudaStreamWaitEvent(0, evG1, 0);
    cudaStreamWaitEvent(0, evCsr, 0);

    // fused gather1 + LN + ReLU + layer-2 GEMM -> h1 (global) + hws2
    k_gather_gemm<<<(N + 127) / 128, 256>>>(c1_b, n1_g, n1_b, c2_w, p_cnt,
                                            p_h1, p_hws2, N);

    // gather2 + skip + readout pooling
    k_gather<<<((size_t)N * 8 + 255) / 256, 256>>>(p_hws2, c2_b, n2_g, n2_b, N, batch);

    // post
    k_post<<<G, 64>>>(post_w, post_b, (float*)d_out, G);
}

// round 15
// speedup vs baseline: 1.2085x; 1.2085x over previous
#include <cuda_runtime.h>
#include <cuda_fp16.h>
#include <mma.h>
#include <cstdint>
#include <cstddef>

using namespace nvcuda;

// Problem constants: N=100000, E=1600000, F=128, H=64, C=40, G=2048
#define NMAX 100000
#define EMAX 1600000
#define GMAX 2048

// ---------------- scratch (device globals; no runtime alloc allowed) ----------------
__device__ __align__(128) __half g_hws[NMAX * 64];  // (h @ W) * isq (fp16) per layer
__device__ __align__(128) __half g_h1 [NMAX * 64];  // layer-1 activations (fp16)
__device__ __align__(16)  float  g_deg[NMAX];       // isq
__device__ __align__(128) float  g_readout[GMAX * 64];
__device__ __align__(16)  int    g_cnt[NMAX];       // per-dst degree
__device__ __align__(16)  int    g_ptr[NMAX];       // CSR row starts
__device__ __align__(16)  int    g_cursor[NMAX];    // fill cursors
__device__ __align__(16)  int    g_csr_src[EMAX];   // CSR column (src) indices
__device__ __align__(16)  __half g_w1h[128 * 72];   // pre_w fp16, padded ld=72
__device__ __align__(16)  __half g_w2h[64 * 72];    // c1_w fp16, padded ld=72
__device__ __align__(16)  __half g_w3h[64 * 72];    // c2_w fp16, padded ld=72
__device__ int g_scanflag[128];                     // lookback published aggregates (+1)
__device__ int g_idx32;                             // 1 if indices are int32

// ---------------- weight pre-conversion (once per launch) ----------------
__global__ void k_cvtw(const float* __restrict__ W1, const float* __restrict__ W2,
                       const float* __restrict__ W3) {
    int i = blockIdx.x * blockDim.x + threadIdx.x;
    if (i < 128 * 64) {
        int r = i >> 6, c = i & 63;
        g_w1h[r * 72 + c] = __float2half(W1[i]);
    }
    if (i < 64 * 64) {
        int r = i >> 6, c = i & 63;
        g_w2h[r * 72 + c] = __float2half(W2[i]);
        g_w3h[r * 72 + c] = __float2half(W3[i]);
    }
}

// ---------------- per-block index-dtype detection ----------------
__device__ __forceinline__ int block_detect_idx32(const void* e, int E, long long nlim,
                                                  int* s_flag) {
    if (threadIdx.x == 0) *s_flag = 0;
    __syncthreads();
    int m = E < 64 ? E : 64;
    if ((int)threadIdx.x < m) {
        long long v = ((const long long*)e)[threadIdx.x];
        if (v < 0 || v >= nlim) *s_flag = 1;
    }
    __syncthreads();
    return *s_flag;
}

// ---------------- degree histogram ----------------
__global__ void __launch_bounds__(256) k_hist(const void* __restrict__ eidx, int E,
                                              long long nlim) {
    __shared__ int sf;
    int idx32 = block_detect_idx32(eidx, E, nlim, &sf);
    if (blockIdx.x == 0 && threadIdx.x == 0) g_idx32 = idx32;
    int base = (blockIdx.x * blockDim.x + threadIdx.x) * 4;
    if (idx32) {
        const int* d = (const int*)eidx + E;
#pragma unroll
        for (int k = 0; k < 4; k++) {
            int e = base + k;
            if (e < E) atomicAdd(&g_cnt[d[e]], 1);
        }
    } else {
        const long long* d = (const long long*)eidx + E;
#pragma unroll
        for (int k = 0; k < 4; k++) {
            int e = base + k;
            if (e < E) atomicAdd(&g_cnt[(int)d[e]], 1);
        }
    }
}

// ---------------- single-pass exclusive scan (lookback) + cursor + isq ----------------
__global__ void __launch_bounds__(256) k_scan(int n) {
    __shared__ int wsum[8];
    __shared__ int red[8];
    __shared__ int s_prefix;
    int bid = blockIdx.x;
    int base = bid * 1024 + threadIdx.x * 4;

    int c0 = 0, c1 = 0, c2 = 0, c3 = 0;
    if (base + 3 < n) {
        int4 c = *(const int4*)&g_cnt[base];
        c0 = c.x; c1 = c.y; c2 = c.z; c3 = c.w;
    } else if (base < n) {
        c0 = g_cnt[base];
        if (base + 1 < n) c1 = g_cnt[base + 1];
        if (base + 2 < n) c2 = g_cnt[base + 2];
    }
    int tot = c0 + c1 + c2 + c3;
    int lane = threadIdx.x & 31, wid = threadIdx.x >> 5;
    int v = tot;
#pragma unroll
    for (int o = 1; o < 32; o <<= 1) {
        int u = __shfl_up_sync(0xffffffffu, v, o);
        if (lane >= o) v += u;
    }
    if (lane == 31) wsum[wid] = v;
    __syncthreads();
    if (threadIdx.x == 0) {
        int s = 0;
        for (int i = 0; i < 8; i++) { int t = wsum[i]; wsum[i] = s; s += t; }
        atomicExch(&g_scanflag[bid], s + 1);
    }
    __syncthreads();

    int part = 0;
    if ((int)threadIdx.x < bid) {
        volatile int* f = &g_scanflag[threadIdx.x];
        int x;
        do { x = *f; } while (x == 0);
        part = x - 1;
    }
#pragma unroll
    for (int o = 16; o; o >>= 1) part += __shfl_xor_sync(0xffffffffu, part, o);
    if (lane == 0) red[wid] = part;
    __syncthreads();
    if (threadIdx.x == 0) {
        int s = 0;
        for (int i = 0; i < 8; i++) s += red[i];
        s_prefix = s;
    }
    __syncthreads();

    int excl = v - tot + wsum[wid] + s_prefix;
    if (base < n) {
        int p0 = excl, p1 = p0 + c0, p2 = p1 + c1, p3 = p2 + c2;
        g_ptr[base] = p0; g_cursor[base] = p0; g_deg[base] = rsqrtf((float)c0 + 1.0f);
        if (base + 1 < n) { g_ptr[base+1] = p1; g_cursor[base+1] = p1; g_deg[base+1] = rsqrtf((float)c1 + 1.0f); }
        if (base + 2 < n) { g_ptr[base+2] = p2; g_cursor[base+2] = p2; g_deg[base+2] = rsqrtf((float)c2 + 1.0f); }
        if (base + 3 < n) { g_ptr[base+3] = p3; g_cursor[base+3] = p3; g_deg[base+3] = rsqrtf((float)c3 + 1.0f); }
    }
}

// ---------------- CSR fill ----------------
__global__ void __launch_bounds__(256) k_fill(const void* __restrict__ eidx, int E,
                                              long long nlim) {
    __shared__ int sf;
    int idx32 = block_detect_idx32(eidx, E, nlim, &sf);
    int base = (blockIdx.x * blockDim.x + threadIdx.x) * 4;
#pragma unroll
    for (int k = 0; k < 4; k++) {
        int e = base + k;
        if (e >= E) break;
        int src, dst;
        if (idx32) {
            const int* p = (const int*)eidx;
            src = p[e]; dst = p[E + e];
        } else {
            const long long* p = (const long long*)eidx;
            src = (int)p[e]; dst = (int)p[E + e];
        }
        int pos = atomicAdd(&g_cursor[dst], 1);
        g_csr_src[pos] = src;
    }
}

// ---------------- fused pre-MLP + layer-1 GEMM: hws = ((x@W1+b1)@W2)*isq -------------
// W staged as uint4 copies from pre-converted fp16 buffers. C1 aliases W1s after
// barrier #2. Warp-local phases otherwise.
__global__ void __launch_bounds__(256) k_gemm0(const float* __restrict__ x,
                                               const float* __restrict__ b1,
                                               const int* __restrict__ cnt,
                                               __half* __restrict__ out, int n) {
    __shared__ __align__(16) char sm[46080];
    __half* W1s = (__half*)sm;                       // 128 x 64, ld 72
    __half* W2s = (__half*)(sm + 18432);             // 64 x 64, ld 72
    __half* As  = (__half*)(sm + 27648);             // 128 x 64, ld 72 (warp strips)
    __half* C1  = W1s;                               // aliased after barrier #2

    int tid = threadIdx.x;
    int warpId = tid >> 5, lane = tid & 31;
    int nodeBase = blockIdx.x * 128;

    {
        const uint4* s1 = (const uint4*)g_w1h;
        uint4* d1 = (uint4*)W1s;
        for (int i = tid; i < 1152; i += 256) d1[i] = s1[i];
        const uint4* s2 = (const uint4*)g_w2h;
        uint4* d2 = (uint4*)W2s;
        for (int i = tid; i < 576; i += 256) d2[i] = s2[i];
    }
    __syncthreads();   // barrier #1: W staged

    __half* Aw   = As + warpId * 1152;   // warp strip: 16 x 72 halfs
    __half* C1w  = C1 + warpId * 1152;
    float*  tmpf = (float*)Aw;           // 16 x 20 fp32 alias (A dead when used)

    int srow = tid >> 1;
    int wrow = srow & 15;
    int scol = (tid & 1) * 32;
    int sgn = nodeBase + srow;
    bool sok = (sgn < n);
    const float* aptr = x + (size_t)sgn * 128 + scol;

    // ---- phase 1: C = x @ W1 (K=128, two 64-col chunks), warp-local ----
    wmma::fragment<wmma::accumulator, 16, 16, 16, float> cf[4];
#pragma unroll
    for (int t = 0; t < 4; t++) wmma::fill_fragment(cf[t], 0.0f);

#pragma unroll
    for (int c = 0; c < 2; c++) {
        __syncwarp();
#pragma unroll
        for (int q = 0; q < 4; q++) {
            float4 f0, f1;
            if (sok) {
                f0 = *(const float4*)(aptr + c * 64 + q * 8);
                f1 = *(const float4*)(aptr + c * 64 + q * 8 + 4);
            } else {
                f0 = make_float4(0.f, 0.f, 0.f, 0.f);
                f1 = f0;
            }
            __align__(16) __half2 hs[4];
            hs[0] = __floats2half2_rn(f0.x, f0.y);
            hs[1] = __floats2half2_rn(f0.z, f0.w);
            hs[2] = __floats2half2_rn(f1.x, f1.y);
            hs[3] = __floats2half2_rn(f1.z, f1.w);
            *(uint4*)(Aw + wrow * 72 + scol + q * 8) = *(const uint4*)hs;
        }
        __syncwarp();
#pragma unroll
        for (int kk = 0; kk < 64; kk += 16) {
            wmma::fragment<wmma::matrix_a, 16, 16, 16, __half, wmma::row_major> af;
            wmma::load_matrix_sync(af, Aw + kk, 72);
#pragma unroll
            for (int t = 0; t < 4; t++) {
                wmma::fragment<wmma::matrix_b, 16, 16, 16, __half, wmma::row_major> bf;
                wmma::load_matrix_sync(bf, W1s + (c * 64 + kk) * 72 + t * 16, 72);
                wmma::mma_sync(cf[t], af, bf, cf[t]);
            }
        }
    }
    __syncthreads();   // barrier #2: W1s dead -> C1 may overwrite it

    // ---- phase 2: cf -> (+b1) -> fp16 C1 (aliased over W1s), warp-local ----
    int tr = lane >> 1;
    int tc = (lane & 1) * 8;
#pragma unroll
    for (int t = 0; t < 4; t++) {
        __syncwarp();
        wmma::store_matrix_sync(tmpf, cf[t], 20, wmma::mem_row_major);
        __syncwarp();
        const float* s = tmpf + tr * 20 + tc;
        float4 v0 = *(const float4*)s;
        float4 v1 = *(const float4*)(s + 4);
        float4 ba = *(const float4*)(b1 + t * 16 + tc);
        float4 bb = *(const float4*)(b1 + t * 16 + tc + 4);
        __align__(16) __half2 hs[4];
        hs[0] = __floats2half2_rn(v0.x + ba.x, v0.y + ba.y);
        hs[1] = __floats2half2_rn(v0.z + ba.z, v0.w + ba.w);
        hs[2] = __floats2half2_rn(v1.x + bb.x, v1.y + bb.y);
        hs[3] = __floats2half2_rn(v1.z + bb.z, v1.w + bb.w);
        __syncwarp();
        *(uint4*)(C1w + tr * 72 + t * 16 + tc) = *(const uint4*)hs;
    }
    __syncwarp();

    // ---- phase 3: D = C1 @ W2 (K=64), warp-local ----
    wmma::fragment<wmma::accumulator, 16, 16, 16, float> cg[4];
#pragma unroll
    for (int t = 0; t < 4; t++) wmma::fill_fragment(cg[t], 0.0f);
#pragma unroll
    for (int kk = 0; kk < 64; kk += 16) {
        wmma::fragment<wmma::matrix_a, 16, 16, 16, __half, wmma::row_major> af;
        wmma::load_matrix_sync(af, C1w + kk, 72);
#pragma unroll
        for (int t = 0; t < 4; t++) {
            wmma::fragment<wmma::matrix_b, 16, 16, 16, __half, wmma::row_major> bf;
            wmma::load_matrix_sync(bf, W2s + kk * 72 + t * 16, 72);
            wmma::mma_sync(cg[t], af, bf, cg[t]);
        }
    }

    // ---- epilogue: *isq, fp16 out ----
    int gn = nodeBase + warpId * 16 + tr;
    float siq = (gn < n) ? rsqrtf((float)__ldg(&cnt[gn]) + 1.0f) : 0.f;
#pragma unroll
    for (int t = 0; t < 4; t++) {
        __syncwarp();
        wmma::store_matrix_sync(tmpf, cg[t], 20, wmma::mem_row_major);
        __syncwarp();
        if (gn < n) {
            const float* s = tmpf + tr * 20 + tc;
            float4 v0 = *(const float4*)s;
            float4 v1 = *(const float4*)(s + 4);
            __align__(16) __half2 p[4];
            p[0] = __floats2half2_rn(v0.x * siq, v0.y * siq);
            p[1] = __floats2half2_rn(v0.z * siq, v0.w * siq);
            p[2] = __floats2half2_rn(v1.x * siq, v1.y * siq);
            p[3] = __floats2half2_rn(v1.z * siq, v1.w * siq);
            *(uint4*)(out + (size_t)gn * 64 + t * 16 + tc) = *(const uint4*)p;
        }
    }
}

// ---------------- layer-2 GEMM: hws = (h1 @ W3)*isq, fp16 in/out ----------------
__global__ void __launch_bounds__(256) k_gemm_h(const __half* __restrict__ A,
                                                const int* __restrict__ cnt,
                                                __half* __restrict__ out, int n) {
    __shared__ __align__(16) __half Ws[64 * 72];
    __shared__ __align__(16) __half As[128 * 72];

    int tid = threadIdx.x;
    int warpId = tid >> 5, lane = tid & 31;
    int nodeBase = blockIdx.x * 128;

    {
        const uint4* s3 = (const uint4*)g_w3h;
        uint4* d3 = (uint4*)Ws;
        for (int i = tid; i < 576; i += 256) d3[i] = s3[i];
    }
    __syncthreads();   // only block barrier

    __half* Aw = As + warpId * 1152;
    float* tmpf = (float*)Aw;

    int srow = tid >> 1;
    int wrow = srow & 15;
    int scol = (tid & 1) * 32;
    int sgn = nodeBase + srow;
    if (sgn < n) {
        const uint4* ap = (const uint4*)(A + (size_t)sgn * 64 + scol);
        uint4* dp = (uint4*)(Aw + wrow * 72 + scol);
        dp[0] = __ldg(&ap[0]); dp[1] = __ldg(&ap[1]);
        dp[2] = __ldg(&ap[2]); dp[3] = __ldg(&ap[3]);
    } else {
        uint4 z = make_uint4(0u, 0u, 0u, 0u);
        uint4* dp = (uint4*)(Aw + wrow * 72 + scol);
        dp[0] = z; dp[1] = z; dp[2] = z; dp[3] = z;
    }
    __syncwarp();

    wmma::fragment<wmma::accumulator, 16, 16, 16, float> cf[4];
#pragma unroll
    for (int t = 0; t < 4; t++) wmma::fill_fragment(cf[t], 0.0f);
#pragma unroll
    for (int kk = 0; kk < 64; kk += 16) {
        wmma::fragment<wmma::matrix_a, 16, 16, 16, __half, wmma::row_major> af;
        wmma::load_matrix_sync(af, Aw + kk, 72);
#pragma unroll
        for (int t = 0; t < 4; t++) {
            wmma::fragment<wmma::matrix_b, 16, 16, 16, __half, wmma::row_major> bf;
            wmma::load_matrix_sync(bf, Ws + kk * 72 + t * 16, 72);
            wmma::mma_sync(cf[t], af, bf, cf[t]);
        }
    }

    int tr = lane >> 1;
    int tc = (lane & 1) * 8;
    int gn = nodeBase + warpId * 16 + tr;
    float siq = (gn < n) ? rsqrtf((float)__ldg(&cnt[gn]) + 1.0f) : 0.f;
#pragma unroll
    for (int t = 0; t < 4; t++) {
        __syncwarp();
        wmma::store_matrix_sync(tmpf, cf[t], 20, wmma::mem_row_major);
        __syncwarp();
        if (gn < n) {
            const float* s = tmpf + tr * 20 + tc;
            float4 v0 = *(const float4*)s;
            float4 v1 = *(const float4*)(s + 4);
            __align__(16) __half2 p[4];
            p[0] = __floats2half2_rn(v0.x * siq, v0.y * siq);
            p[1] = __floats2half2_rn(v0.z * siq, v0.w * siq);
            p[2] = __floats2half2_rn(v1.x * siq, v1.y * siq);
            p[3] = __floats2half2_rn(v1.z * siq, v1.w * siq);
            *(uint4*)(out + (size_t)gn * 64 + t * 16 + tc) = *(const uint4*)p;
        }
    }
}

// ---------------- fused gather + self + bias + LN + ReLU (+skip+readout) -------------
// 4 independent nodes per warp, 8 lanes x uint4 per row. h1 output/skip in fp16.
__global__ void __launch_bounds__(256) k_gather(const float* __restrict__ bias,
                                                const float* __restrict__ lng,
                                                const float* __restrict__ lnb,
                                                __half* __restrict__ outh, int n,
                                                int do_readout,
                                                const void* __restrict__ batch) {
    const unsigned FULL = 0xffffffffu;
    int t = blockIdx.x * blockDim.x + threadIdx.x;
    int node = t >> 3;
    int lane = threadIdx.x & 31;
    int grp = lane >> 3, sub = lane & 7;
    bool ok = (node < n);
    int nodec = ok ? node : (n - 1);

    int start = g_ptr[nodec];
    int cnt   = ok ? g_cnt[nodec] : 0;

    int mmax = cnt;
    mmax = max(mmax, __shfl_xor_sync(FULL, mmax, 8));
    mmax = max(mmax, __shfl_xor_sync(FULL, mmax, 16));

    const uint4* hw4 = (const uint4*)g_hws;
    __half2 acc[4];
    __half2 z = __float2half2_rn(0.f);
#pragma unroll
    for (int k = 0; k < 4; k++) acc[k] = z;

    for (int done = 0; done < mmax; done += 8) {
        int b = 0;
        if (done + sub < cnt) b = __ldg(&g_csr_src[start + done + sub]);
        int lim = cnt - done;
        uint4 v[8];
#pragma unroll
        for (int j = 0; j < 8; j++) {
            int s = __shfl_sync(FULL, b, (grp << 3) + j);
            v[j] = make_uint4(0u, 0u, 0u, 0u);
            if (j < lim) v[j] = __ldg(&hw4[(size_t)s * 8 + sub]);
        }
#pragma unroll
        for (int j = 0; j < 8; j++) {
            const __half2* p = (const __half2*)&v[j];
            acc[0] = __hadd2(acc[0], p[0]);
            acc[1] = __hadd2(acc[1], p[1]);
            acc[2] = __hadd2(acc[2], p[2]);
            acc[3] = __hadd2(acc[3], p[3]);
        }
    }

    uint4 sv = __ldg(&hw4[(size_t)nodec * 8 + sub]);
    const __half2* ps = (const __half2*)&sv;
    float isqn = g_deg[nodec];
    const float4* b4 = (const float4*)bias;
    float4 bl = __ldg(&b4[sub * 2]), bh = __ldg(&b4[sub * 2 + 1]);
    float bb[8] = {bl.x, bl.y, bl.z, bl.w, bh.x, bh.y, bh.z, bh.w};

    float v8[8];
#pragma unroll
    for (int k = 0; k < 4; k++) {
        float2 f  = __half22float2(acc[k]);
        float2 fs = __half22float2(ps[k]);
        v8[2 * k]     = fmaf(isqn, f.x + fs.x, bb[2 * k]);
        v8[2 * k + 1] = fmaf(isqn, f.y + fs.y, bb[2 * k + 1]);
    }

    float sum = 0.f;
#pragma unroll
    for (int i = 0; i < 8; i++) sum += v8[i];
#pragma unroll
    for (int o = 4; o; o >>= 1) sum += __shfl_xor_sync(FULL, sum, o);
    float mu = sum * (1.0f / 64.0f);

    float var = 0.f, d8[8];
#pragma unroll
    for (int i = 0; i < 8; i++) { d8[i] = v8[i] - mu; var += d8[i] * d8[i]; }
#pragma unroll
    for (int o = 4; o; o >>= 1) var += __shfl_xor_sync(FULL, var, o);
    float rstd = rsqrtf(var * (1.0f / 64.0f) + 1e-5f);

    const float4* g4 = (const float4*)lng;
    const float4* l4 = (const float4*)lnb;
    float4 gl = __ldg(&g4[sub * 2]), gh = __ldg(&g4[sub * 2 + 1]);
    float4 ll = __ldg(&l4[sub * 2]), lh = __ldg(&l4[sub * 2 + 1]);
    float gg[8] = {gl.x, gl.y, gl.z, gl.w, gh.x, gh.y, gh.z, gh.w};
    float lb[8] = {ll.x, ll.y, ll.z, ll.w, lh.x, lh.y, lh.z, lh.w};

    float o8[8];
#pragma unroll
    for (int i = 0; i < 8; i++)
        o8[i] = fmaxf(fmaf(d8[i] * rstd, gg[i], lb[i]), 0.f);

    if (!ok) return;
    if (!do_readout) {
        __align__(16) __half2 p[4];
        p[0] = __floats2half2_rn(o8[0], o8[1]);
        p[1] = __floats2half2_rn(o8[2], o8[3]);
        p[2] = __floats2half2_rn(o8[4], o8[5]);
        p[3] = __floats2half2_rn(o8[6], o8[7]);
        *(uint4*)(outh + (size_t)node * 64 + sub * 8) = *(const uint4*)p;
    } else {
        uint4 hv = __ldg((const uint4*)(g_h1 + (size_t)node * 64 + sub * 8));
        const __half2* ph = (const __half2*)&hv;
        float h8[8];
#pragma unroll
        for (int k = 0; k < 4; k++) {
            float2 f = __half22float2(ph[k]);
            h8[2 * k] = f.x; h8[2 * k + 1] = f.y;
        }
        int grpi = g_idx32 ? ((const int*)batch)[node]
                           : (int)((const long long*)batch)[node];
        float4* r4 = (float4*)(g_readout + (size_t)grpi * 64 + sub * 8);
        atomicAdd(&r4[0], make_float4(o8[0] + h8[0], o8[1] + h8[1], o8[2] + h8[2], o8[3] + h8[3]));
        atomicAdd(&r4[1], make_float4(o8[4] + h8[4], o8[5] + h8[5], o8[6] + h8[6], o8[7] + h8[7]));
    }
}

// ---------------- post GEMM: 4 graphs per block ----------------
__global__ void __launch_bounds__(256) k_post(const float* __restrict__ W,
                                              const float* __restrict__ b,
                                              float* __restrict__ out, int G) {
    __shared__ float r[4][64];
    int sgrp = threadIdx.x >> 6;
    int lidx = threadIdx.x & 63;
    int g = blockIdx.x * 4 + sgrp;
    if (g < G) r[sgrp][lidx] = g_readout[(size_t)g * 64 + lidx];
    __syncthreads();
    if (g < G && lidx < 40) {
        float acc = b[lidx];
#pragma unroll
        for (int k = 0; k < 64; k++) acc = fmaf(r[sgrp][k], __ldg(&W[k * 40 + lidx]), acc);
        out[(size_t)g * 40 + lidx] = acc;
    }
}

// ---------------- launch: cvtw(1) hist(2) scan(3) gemm0(4=ncu) fill(5) ... -----------
extern "C" void kernel_launch(void* const* d_in, const int* in_sizes, int n_in,
                              void* d_out, int out_size) {
    const float* x      = (const float*)d_in[0];
    const void*  eidx   = d_in[1];
    const void*  batch  = d_in[2];
    const float* pre_w  = (const float*)d_in[3];
    const float* pre_b  = (const float*)d_in[4];
    const float* c1_w   = (const float*)d_in[5];
    const float* c1_b   = (const float*)d_in[6];
    const float* n1_g   = (const float*)d_in[7];
    const float* n1_b   = (const float*)d_in[8];
    const float* c2_w   = (const float*)d_in[9];
    const float* c2_b   = (const float*)d_in[10];
    const float* n2_g   = (const float*)d_in[11];
    const float* n2_b   = (const float*)d_in[12];
    const float* post_w = (const float*)d_in[13];
    const float* post_b = (const float*)d_in[14];

    int N = in_sizes[0] / 128;
    int E = in_sizes[1] / 2;
    int G = out_size / 40;

    float* p_readout;
    __half *p_hws, *p_h1;
    int *p_cnt, *p_flag;
    cudaGetSymbolAddress((void**)&p_hws,     g_hws);
    cudaGetSymbolAddress((void**)&p_h1,      g_h1);
    cudaGetSymbolAddress((void**)&p_cnt,     g_cnt);
    cudaGetSymbolAddress((void**)&p_flag,    g_scanflag);
    cudaGetSymbolAddress((void**)&p_readout, g_readout);

    static cudaStream_t s1 = nullptr, s2 = nullptr;
    static cudaEvent_t evFork = nullptr, evHist = nullptr, evG1 = nullptr, evCsr = nullptr;
    if (!s1) {
        cudaStreamCreateWithFlags(&s1, cudaStreamNonBlocking);
        cudaStreamCreateWithFlags(&s2, cudaStreamNonBlocking);
        cudaEventCreateWithFlags(&evFork, cudaEventDisableTiming);
        cudaEventCreateWithFlags(&evHist, cudaEventDisableTiming);
        cudaEventCreateWithFlags(&evG1,   cudaEventDisableTiming);
        cudaEventCreateWithFlags(&evCsr,  cudaEventDisableTiming);
    }

    cudaEventRecord(evFork, 0);
    cudaStreamWaitEvent(s1, evFork, 0);
    cudaStreamWaitEvent(s2, evFork, 0);

    // --- s1: weight pre-conversion (#1) ---
    k_cvtw<<<32, 256, 0, s1>>>(pre_w, c1_w, c2_w);

    // --- s2: memsets + hist (#2) ---
    cudaMemsetAsync(p_cnt, 0, (size_t)N * 4, s2);
    cudaMemsetAsync(p_flag, 0, 128 * 4, s2);
    cudaMemsetAsync(p_readout, 0, (size_t)G * 64 * 4, s2);
    k_hist<<<(E + 1023) / 1024, 256, 0, s2>>>(eidx, E, (long long)N);
    cudaEventRecord(evHist, s2);

    // --- s2: scan (#3) ---
    k_scan<<<(N + 1023) / 1024, 256, 0, s2>>>(N);

    // --- s1: fused pre-MLP + layer-1 GEMM (#4 -> ncu -s 5 slot) ---
    cudaStreamWaitEvent(s1, evHist, 0);
    k_gemm0<<<(N + 127) / 128, 256, 0, s1>>>(x, pre_b, p_cnt, p_hws, N);
    cudaEventRecord(evG1, s1);

    // --- s2: fill (#5) ---
    k_fill<<<(E + 1023) / 1024, 256, 0, s2>>>(eidx, E, (long long)N);
    cudaEventRecord(evCsr, s2);

    // --- join ---
    cudaStreamWaitEvent(0, evG1, 0);
    cudaStreamWaitEvent(0, evCsr, 0);

    // layer 1 gather -> h1 (fp16) (#6)
    k_gather<<<((size_t)N * 8 + 255) / 256, 256>>>(c1_b, n1_g, n1_b, p_h1, N, 0, nullptr);

    // layer 2 (#7, #8)
    k_gemm_h<<<(N + 127) / 128, 256>>>(p_h1, p_cnt, p_hws, N);
    k_gather<<<((size_t)N * 8 + 255) / 256, 256>>>(c2_b, n2_g, n2_b, nullptr, N, 1, batch);

    // post (#9)
    k_post<<<(G + 3) / 4, 256>>>(post_w, post_b, (float*)d_out, G);
}

// round 16
// speedup vs baseline: 1.2088x; 1.0002x over previous
#include <cuda_runtime.h>
#include <cuda_fp16.h>
#include <mma.h>
#include <cstdint>
#include <cstddef>

using namespace nvcuda;

// Problem constants: N=100000, E=1600000, F=128, H=64, C=40, G=2048
#define NMAX 100000
#define EMAX 1600000
#define GMAX 2048

// ---------------- scratch (device globals; no runtime alloc allowed) ----------------
__device__ __align__(128) __half g_xh [NMAX * 128]; // x in fp16
__device__ __align__(128) __half g_hws[NMAX * 64];  // (h @ W) * isq (fp16) per layer
__device__ __align__(128) __half g_h1 [NMAX * 64];  // layer-1 activations (fp16)
__device__ __align__(16)  float  g_deg[NMAX];       // isq
__device__ __align__(128) float  g_readout[GMAX * 64];
__device__ __align__(16)  int    g_cnt[NMAX];       // per-dst degree
__device__ __align__(16)  int    g_ptr[NMAX];       // CSR row starts
__device__ __align__(16)  int    g_cursor[NMAX];    // fill cursors
__device__ __align__(16)  int    g_csr_src[EMAX];   // CSR column (src) indices
__device__ __align__(16)  __half g_w1h[128 * 72];   // pre_w fp16, padded ld=72
__device__ __align__(16)  __half g_w2h[64 * 72];    // c1_w fp16, padded ld=72
__device__ __align__(16)  __half g_w3h[64 * 72];    // c2_w fp16, padded ld=72
__device__ int g_scanflag[128];                     // lookback published aggregates (+1)
__device__ int g_idx32;                             // 1 if indices are int32

// ---------------- weight pre-conversion ----------------
__global__ void k_cvtw(const float* __restrict__ W1, const float* __restrict__ W2,
                       const float* __restrict__ W3) {
    int i = blockIdx.x * blockDim.x + threadIdx.x;
    if (i < 128 * 64) {
        int r = i >> 6, c = i & 63;
        g_w1h[r * 72 + c] = __float2half(W1[i]);
    }
    if (i < 64 * 64) {
        int r = i >> 6, c = i & 63;
        g_w2h[r * 72 + c] = __float2half(W2[i]);
        g_w3h[r * 72 + c] = __float2half(W3[i]);
    }
}

// ---------------- x fp32 -> fp16 streaming conversion ----------------
__global__ void __launch_bounds__(256) k_cvtx(const float* __restrict__ x, int total8) {
    int i = blockIdx.x * blockDim.x + threadIdx.x;   // one uint4 out = 8 halfs
    if (i >= total8) return;
    const float4* src = (const float4*)x + (size_t)i * 2;
    float4 f0 = __ldg(&src[0]);
    float4 f1 = __ldg(&src[1]);
    __align__(16) __half2 h[4];
    h[0] = __floats2half2_rn(f0.x, f0.y);
    h[1] = __floats2half2_rn(f0.z, f0.w);
    h[2] = __floats2half2_rn(f1.x, f1.y);
    h[3] = __floats2half2_rn(f1.z, f1.w);
    ((uint4*)g_xh)[i] = *(const uint4*)h;
}

// ---------------- per-block index-dtype detection ----------------
__device__ __forceinline__ int block_detect_idx32(const void* e, int E, long long nlim,
                                                  int* s_flag) {
    if (threadIdx.x == 0) *s_flag = 0;
    __syncthreads();
    int m = E < 64 ? E : 64;
    if ((int)threadIdx.x < m) {
        long long v = ((const long long*)e)[threadIdx.x];
        if (v < 0 || v >= nlim) *s_flag = 1;
    }
    __syncthreads();
    return *s_flag;
}

// ---------------- degree histogram ----------------
__global__ void __launch_bounds__(256) k_hist(const void* __restrict__ eidx, int E,
                                              long long nlim) {
    __shared__ int sf;
    int idx32 = block_detect_idx32(eidx, E, nlim, &sf);
    if (blockIdx.x == 0 && threadIdx.x == 0) g_idx32 = idx32;
    int base = (blockIdx.x * blockDim.x + threadIdx.x) * 4;
    if (idx32) {
        const int* d = (const int*)eidx + E;
#pragma unroll
        for (int k = 0; k < 4; k++) {
            int e = base + k;
            if (e < E) atomicAdd(&g_cnt[d[e]], 1);
        }
    } else {
        const long long* d = (const long long*)eidx + E;
#pragma unroll
        for (int k = 0; k < 4; k++) {
            int e = base + k;
            if (e < E) atomicAdd(&g_cnt[(int)d[e]], 1);
        }
    }
}

// ---------------- single-pass exclusive scan (lookback) + cursor + isq ----------------
__global__ void __launch_bounds__(256) k_scan(int n) {
    __shared__ int wsum[8];
    __shared__ int red[8];
    __shared__ int s_prefix;
    int bid = blockIdx.x;
    int base = bid * 1024 + threadIdx.x * 4;

    int c0 = 0, c1 = 0, c2 = 0, c3 = 0;
    if (base + 3 < n) {
        int4 c = *(const int4*)&g_cnt[base];
        c0 = c.x; c1 = c.y; c2 = c.z; c3 = c.w;
    } else if (base < n) {
        c0 = g_cnt[base];
        if (base + 1 < n) c1 = g_cnt[base + 1];
        if (base + 2 < n) c2 = g_cnt[base + 2];
    }
    int tot = c0 + c1 + c2 + c3;
    int lane = threadIdx.x & 31, wid = threadIdx.x >> 5;
    int v = tot;
#pragma unroll
    for (int o = 1; o < 32; o <<= 1) {
        int u = __shfl_up_sync(0xffffffffu, v, o);
        if (lane >= o) v += u;
    }
    if (lane == 31) wsum[wid] = v;
    __syncthreads();
    if (threadIdx.x == 0) {
        int s = 0;
        for (int i = 0; i < 8; i++) { int t = wsum[i]; wsum[i] = s; s += t; }
        atomicExch(&g_scanflag[bid], s + 1);
    }
    __syncthreads();

    int part = 0;
    if ((int)threadIdx.x < bid) {
        volatile int* f = &g_scanflag[threadIdx.x];
        int x;
        do { x = *f; } while (x == 0);
        part = x - 1;
    }
#pragma unroll
    for (int o = 16; o; o >>= 1) part += __shfl_xor_sync(0xffffffffu, part, o);
    if (lane == 0) red[wid] = part;
    __syncthreads();
    if (threadIdx.x == 0) {
        int s = 0;
        for (int i = 0; i < 8; i++) s += red[i];
        s_prefix = s;
    }
    __syncthreads();

    int excl = v - tot + wsum[wid] + s_prefix;
    if (base < n) {
        int p0 = excl, p1 = p0 + c0, p2 = p1 + c1, p3 = p2 + c2;
        g_ptr[base] = p0; g_cursor[base] = p0; g_deg[base] = rsqrtf((float)c0 + 1.0f);
        if (base + 1 < n) { g_ptr[base+1] = p1; g_cursor[base+1] = p1; g_deg[base+1] = rsqrtf((float)c1 + 1.0f); }
        if (base + 2 < n) { g_ptr[base+2] = p2; g_cursor[base+2] = p2; g_deg[base+2] = rsqrtf((float)c2 + 1.0f); }
        if (base + 3 < n) { g_ptr[base+3] = p3; g_cursor[base+3] = p3; g_deg[base+3] = rsqrtf((float)c3 + 1.0f); }
    }
}

// ---------------- CSR fill ----------------
__global__ void __launch_bounds__(256) k_fill(const void* __restrict__ eidx, int E,
                                              long long nlim) {
    __shared__ int sf;
    int idx32 = block_detect_idx32(eidx, E, nlim, &sf);
    int base = (blockIdx.x * blockDim.x + threadIdx.x) * 4;
#pragma unroll
    for (int k = 0; k < 4; k++) {
        int e = base + k;
        if (e >= E) break;
        int src, dst;
        if (idx32) {
            const int* p = (const int*)eidx;
            src = p[e]; dst = p[E + e];
        } else {
            const long long* p = (const long long*)eidx;
            src = (int)p[e]; dst = (int)p[E + e];
        }
        int pos = atomicAdd(&g_cursor[dst], 1);
        g_csr_src[pos] = src;
    }
}

// ---------------- fused pre-MLP + layer-1 GEMM: hws = ((xh@W1+b1)@W2)*isq ------------
// All inputs fp16; A staging is pure uint4 copy. C1 aliases W1s after barrier #2.
__global__ void __launch_bounds__(256) k_gemm0(const float* __restrict__ b1,
                                               const int* __restrict__ cnt,
                                               __half* __restrict__ out, int n) {
    __shared__ __align__(16) char sm[46080];
    __half* W1s = (__half*)sm;                       // 128 x 64, ld 72
    __half* W2s = (__half*)(sm + 18432);             // 64 x 64, ld 72
    __half* As  = (__half*)(sm + 27648);             // 128 x 64, ld 72 (warp strips)
    __half* C1  = W1s;                               // aliased after barrier #2

    int tid = threadIdx.x;
    int warpId = tid >> 5, lane = tid & 31;
    int nodeBase = blockIdx.x * 128;

    {
        const uint4* s1 = (const uint4*)g_w1h;
        uint4* d1 = (uint4*)W1s;
        for (int i = tid; i < 1152; i += 256) d1[i] = s1[i];
        const uint4* s2 = (const uint4*)g_w2h;
        uint4* d2 = (uint4*)W2s;
        for (int i = tid; i < 576; i += 256) d2[i] = s2[i];
    }
    __syncthreads();   // barrier #1: W staged

    __half* Aw   = As + warpId * 1152;   // warp strip: 16 x 72 halfs
    __half* C1w  = C1 + warpId * 1152;
    float*  tmpf = (float*)Aw;           // 16 x 20 fp32 alias (A dead when used)

    int srow = tid >> 1;
    int wrow = srow & 15;
    int scol = (tid & 1) * 32;
    int sgn = nodeBase + srow;
    bool sok = (sgn < n);
    const __half* aptr = g_xh + (size_t)sgn * 128 + scol;

    // ---- phase 1: C = xh @ W1 (K=128, two 64-col chunks), warp-local ----
    wmma::fragment<wmma::accumulator, 16, 16, 16, float> cf[4];
#pragma unroll
    for (int t = 0; t < 4; t++) wmma::fill_fragment(cf[t], 0.0f);

#pragma unroll
    for (int c = 0; c < 2; c++) {
        __syncwarp();
        {
            uint4 v0, v1, v2, v3;
            if (sok) {
                const uint4* ap = (const uint4*)(aptr + c * 64);
                v0 = __ldg(&ap[0]); v1 = __ldg(&ap[1]);
                v2 = __ldg(&ap[2]); v3 = __ldg(&ap[3]);
            } else {
                v0 = v1 = v2 = v3 = make_uint4(0u, 0u, 0u, 0u);
            }
            uint4* dp = (uint4*)(Aw + wrow * 72 + scol);
            dp[0] = v0; dp[1] = v1; dp[2] = v2; dp[3] = v3;
        }
        __syncwarp();
#pragma unroll
        for (int kk = 0; kk < 64; kk += 16) {
            wmma::fragment<wmma::matrix_a, 16, 16, 16, __half, wmma::row_major> af;
            wmma::load_matrix_sync(af, Aw + kk, 72);
#pragma unroll
            for (int t = 0; t < 4; t++) {
                wmma::fragment<wmma::matrix_b, 16, 16, 16, __half, wmma::row_major> bf;
                wmma::load_matrix_sync(bf, W1s + (c * 64 + kk) * 72 + t * 16, 72);
                wmma::mma_sync(cf[t], af, bf, cf[t]);
            }
        }
    }
    __syncthreads();   // barrier #2: W1s dead -> C1 may overwrite it

    // ---- phase 2: cf -> (+b1) -> fp16 C1 (aliased over W1s), warp-local ----
    int tr = lane >> 1;
    int tc = (lane & 1) * 8;
#pragma unroll
    for (int t = 0; t < 4; t++) {
        __syncwarp();
        wmma::store_matrix_sync(tmpf, cf[t], 20, wmma::mem_row_major);
        __syncwarp();
        const float* s = tmpf + tr * 20 + tc;
        float4 v0 = *(const float4*)s;
        float4 v1 = *(const float4*)(s + 4);
        float4 ba = *(const float4*)(b1 + t * 16 + tc);
        float4 bb = *(const float4*)(b1 + t * 16 + tc + 4);
        __align__(16) __half2 hs[4];
        hs[0] = __floats2half2_rn(v0.x + ba.x, v0.y + ba.y);
        hs[1] = __floats2half2_rn(v0.z + ba.z, v0.w + ba.w);
        hs[2] = __floats2half2_rn(v1.x + bb.x, v1.y + bb.y);
        hs[3] = __floats2half2_rn(v1.z + bb.z, v1.w + bb.w);
        __syncwarp();
        *(uint4*)(C1w + tr * 72 + t * 16 + tc) = *(const uint4*)hs;
    }
    __syncwarp();

    // ---- phase 3: D = C1 @ W2 (K=64), warp-local ----
    wmma::fragment<wmma::accumulator, 16, 16, 16, float> cg[4];
#pragma unroll
    for (int t = 0; t < 4; t++) wmma::fill_fragment(cg[t], 0.0f);
#pragma unroll
    for (int kk = 0; kk < 64; kk += 16) {
        wmma::fragment<wmma::matrix_a, 16, 16, 16, __half, wmma::row_major> af;
        wmma::load_matrix_sync(af, C1w + kk, 72);
#pragma unroll
        for (int t = 0; t < 4; t++) {
            wmma::fragment<wmma::matrix_b, 16, 16, 16, __half, wmma::row_major> bf;
            wmma::load_matrix_sync(bf, W2s + kk * 72 + t * 16, 72);
            wmma::mma_sync(cg[t], af, bf, cg[t]);
        }
    }

    // ---- epilogue: *isq, fp16 out ----
    int gn = nodeBase + warpId * 16 + tr;
    float siq = (gn < n) ? rsqrtf((float)__ldg(&cnt[gn]) + 1.0f) : 0.f;
#pragma unroll
    for (int t = 0; t < 4; t++) {
        __syncwarp();
        wmma::store_matrix_sync(tmpf, cg[t], 20, wmma::mem_row_major);
        __syncwarp();
        if (gn < n) {
            const float* s = tmpf + tr * 20 + tc;
            float4 v0 = *(const float4*)s;
            float4 v1 = *(const float4*)(s + 4);
            __align__(16) __half2 p[4];
            p[0] = __floats2half2_rn(v0.x * siq, v0.y * siq);
            p[1] = __floats2half2_rn(v0.z * siq, v0.w * siq);
            p[2] = __floats2half2_rn(v1.x * siq, v1.y * siq);
            p[3] = __floats2half2_rn(v1.z * siq, v1.w * siq);
            *(uint4*)(out + (size_t)gn * 64 + t * 16 + tc) = *(const uint4*)p;
        }
    }
}

// ---------------- layer-2 GEMM: hws = (h1 @ W3)*isq, fp16 in/out ----------------
__global__ void __launch_bounds__(256) k_gemm_h(const __half* __restrict__ A,
                                                const int* __restrict__ cnt,
                                                __half* __restrict__ out, int n) {
    __shared__ __align__(16) __half Ws[64 * 72];
    __shared__ __align__(16) __half As[128 * 72];

    int tid = threadIdx.x;
    int warpId = tid >> 5, lane = tid & 31;
    int nodeBase = blockIdx.x * 128;

    {
        const uint4* s3 = (const uint4*)g_w3h;
        uint4* d3 = (uint4*)Ws;
        for (int i = tid; i < 576; i += 256) d3[i] = s3[i];
    }
    __syncthreads();   // only block barrier

    __half* Aw = As + warpId * 1152;
    float* tmpf = (float*)Aw;

    int srow = tid >> 1;
    int wrow = srow & 15;
    int scol = (tid & 1) * 32;
    int sgn = nodeBase + srow;
    if (sgn < n) {
        const uint4* ap = (const uint4*)(A + (size_t)sgn * 64 + scol);
        uint4* dp = (uint4*)(Aw + wrow * 72 + scol);
        dp[0] = __ldg(&ap[0]); dp[1] = __ldg(&ap[1]);
        dp[2] = __ldg(&ap[2]); dp[3] = __ldg(&ap[3]);
    } else {
        uint4 z = make_uint4(0u, 0u, 0u, 0u);
        uint4* dp = (uint4*)(Aw + wrow * 72 + scol);
        dp[0] = z; dp[1] = z; dp[2] = z; dp[3] = z;
    }
    __syncwarp();

    wmma::fragment<wmma::accumulator, 16, 16, 16, float> cf[4];
#pragma unroll
    for (int t = 0; t < 4; t++) wmma::fill_fragment(cf[t], 0.0f);
#pragma unroll
    for (int kk = 0; kk < 64; kk += 16) {
        wmma::fragment<wmma::matrix_a, 16, 16, 16, __half, wmma::row_major> af;
        wmma::load_matrix_sync(af, Aw + kk, 72);
#pragma unroll
        for (int t = 0; t < 4; t++) {
            wmma::fragment<wmma::matrix_b, 16, 16, 16, __half, wmma::row_major> bf;
            wmma::load_matrix_sync(bf, Ws + kk * 72 + t * 16, 72);
            wmma::mma_sync(cf[t], af, bf, cf[t]);
        }
    }

    int tr = lane >> 1;
    int tc = (lane & 1) * 8;
    int gn = nodeBase + warpId * 16 + tr;
    float siq = (gn < n) ? rsqrtf((float)__ldg(&cnt[gn]) + 1.0f) : 0.f;
#pragma unroll
    for (int t = 0; t < 4; t++) {
        __syncwarp();
        wmma::store_matrix_sync(tmpf, cf[t], 20, wmma::mem_row_major);
        __syncwarp();
        if (gn < n) {
            const float* s = tmpf + tr * 20 + tc;
            float4 v0 = *(const float4*)s;
            float4 v1 = *(const float4*)(s + 4);
            __align__(16) __half2 p[4];
            p[0] = __floats2half2_rn(v0.x * siq, v0.y * siq);
            p[1] = __floats2half2_rn(v0.z * siq, v0.w * siq);
            p[2] = __floats2half2_rn(v1.x * siq, v1.y * siq);
            p[3] = __floats2half2_rn(v1.z * siq, v1.w * siq);
            *(uint4*)(out + (size_t)gn * 64 + t * 16 + tc) = *(const uint4*)p;
        }
    }
}

// ---------------- fused gather + self + bias + LN + ReLU (+skip+readout) -------------
__global__ void __launch_bounds__(256) k_gather(const float* __restrict__ bias,
                                                const float* __restrict__ lng,
                                                const float* __restrict__ lnb,
                                                __half* __restrict__ outh, int n,
                                                int do_readout,
                                                const void* __restrict__ batch) {
    const unsigned FULL = 0xffffffffu;
    int t = blockIdx.x * blockDim.x + threadIdx.x;
    int node = t >> 3;
    int lane = threadIdx.x & 31;
    int grp = lane >> 3, sub = lane & 7;
    bool ok = (node < n);
    int nodec = ok ? node : (n - 1);

    int start = g_ptr[nodec];
    int cnt   = ok ? g_cnt[nodec] : 0;

    int mmax = cnt;
    mmax = max(mmax, __shfl_xor_sync(FULL, mmax, 8));
    mmax = max(mmax, __shfl_xor_sync(FULL, mmax, 16));

    const uint4* hw4 = (const uint4*)g_hws;
    __half2 acc[4];
    __half2 z = __float2half2_rn(0.f);
#pragma unroll
    for (int k = 0; k < 4; k++) acc[k] = z;

    for (int done = 0; done < mmax; done += 8) {
        int b = 0;
        if (done + sub < cnt) b = __ldg(&g_csr_src[start + done + sub]);
        int lim = cnt - done;
        uint4 v[8];
#pragma unroll
        for (int j = 0; j < 8; j++) {
            int s = __shfl_sync(FULL, b, (grp << 3) + j);
            v[j] = make_uint4(0u, 0u, 0u, 0u);
            if (j < lim) v[j] = __ldg(&hw4[(size_t)s * 8 + sub]);
        }
#pragma unroll
        for (int j = 0; j < 8; j++) {
            const __half2* p = (const __half2*)&v[j];
            acc[0] = __hadd2(acc[0], p[0]);
            acc[1] = __hadd2(acc[1], p[1]);
            acc[2] = __hadd2(acc[2], p[2]);
            acc[3] = __hadd2(acc[3], p[3]);
        }
    }

    uint4 sv = __ldg(&hw4[(size_t)nodec * 8 + sub]);
    const __half2* ps = (const __half2*)&sv;
    float isqn = g_deg[nodec];
    const float4* b4 = (const float4*)bias;
    float4 bl = __ldg(&b4[sub * 2]), bh = __ldg(&b4[sub * 2 + 1]);
    float bb[8] = {bl.x, bl.y, bl.z, bl.w, bh.x, bh.y, bh.z, bh.w};

    float v8[8];
#pragma unroll
    for (int k = 0; k < 4; k++) {
        float2 f  = __half22float2(acc[k]);
        float2 fs = __half22float2(ps[k]);
        v8[2 * k]     = fmaf(isqn, f.x + fs.x, bb[2 * k]);
        v8[2 * k + 1] = fmaf(isqn, f.y + fs.y, bb[2 * k + 1]);
    }

    float sum = 0.f;
#pragma unroll
    for (int i = 0; i < 8; i++) sum += v8[i];
#pragma unroll
    for (int o = 4; o; o >>= 1) sum += __shfl_xor_sync(FULL, sum, o);
    float mu = sum * (1.0f / 64.0f);

    float var = 0.f, d8[8];
#pragma unroll
    for (int i = 0; i < 8; i++) { d8[i] = v8[i] - mu; var += d8[i] * d8[i]; }
#pragma unroll
    for (int o = 4; o; o >>= 1) var += __shfl_xor_sync(FULL, var, o);
    float rstd = rsqrtf(var * (1.0f / 64.0f) + 1e-5f);

    const float4* g4 = (const float4*)lng;
    const float4* l4 = (const float4*)lnb;
    float4 gl = __ldg(&g4[sub * 2]), gh = __ldg(&g4[sub * 2 + 1]);
    float4 ll = __ldg(&l4[sub * 2]), lh = __ldg(&l4[sub * 2 + 1]);
    float gg[8] = {gl.x, gl.y, gl.z, gl.w, gh.x, gh.y, gh.z, gh.w};
    float lb[8] = {ll.x, ll.y, ll.z, ll.w, lh.x, lh.y, lh.z, lh.w};

    float o8[8];
#pragma unroll
    for (int i = 0; i < 8; i++)
        o8[i] = fmaxf(fmaf(d8[i] * rstd, gg[i], lb[i]), 0.f);

    if (!ok) return;
    if (!do_readout) {
        __align__(16) __half2 p[4];
        p[0] = __floats2half2_rn(o8[0], o8[1]);
        p[1] = __floats2half2_rn(o8[2], o8[3]);
        p[2] = __floats2half2_rn(o8[4], o8[5]);
        p[3] = __floats2half2_rn(o8[6], o8[7]);
        *(uint4*)(outh + (size_t)node * 64 + sub * 8) = *(const uint4*)p;
    } else {
        uint4 hv = __ldg((const uint4*)(g_h1 + (size_t)node * 64 + sub * 8));
        const __half2* ph = (const __half2*)&hv;
        float h8[8];
#pragma unroll
        for (int k = 0; k < 4; k++) {
            float2 f = __half22float2(ph[k]);
            h8[2 * k] = f.x; h8[2 * k + 1] = f.y;
        }
        int grpi = g_idx32 ? ((const int*)batch)[node]
                           : (int)((const long long*)batch)[node];
        float4* r4 = (float4*)(g_readout + (size_t)grpi * 64 + sub * 8);
        atomicAdd(&r4[0], make_float4(o8[0] + h8[0], o8[1] + h8[1], o8[2] + h8[2], o8[3] + h8[3]));
        atomicAdd(&r4[1], make_float4(o8[4] + h8[4], o8[5] + h8[5], o8[6] + h8[6], o8[7] + h8[7]));
    }
}

// ---------------- post GEMM: 4 graphs per block ----------------
__global__ void __launch_bounds__(256) k_post(const float* __restrict__ W,
                                              const float* __restrict__ b,
                                              float* __restrict__ out, int G) {
    __shared__ float r[4][64];
    int sgrp = threadIdx.x >> 6;
    int lidx = threadIdx.x & 63;
    int g = blockIdx.x * 4 + sgrp;
    if (g < G) r[sgrp][lidx] = g_readout[(size_t)g * 64 + lidx];
    __syncthreads();
    if (g < G && lidx < 40) {
        float acc = b[lidx];
#pragma unroll
        for (int k = 0; k < 64; k++) acc = fmaf(r[sgrp][k], __ldg(&W[k * 40 + lidx]), acc);
        out[(size_t)g * 40 + lidx] = acc;
    }
}

// ---------------- launch ----------------
extern "C" void kernel_launch(void* const* d_in, const int* in_sizes, int n_in,
                              void* d_out, int out_size) {
    const float* x      = (const float*)d_in[0];
    const void*  eidx   = d_in[1];
    const void*  batch  = d_in[2];
    const float* pre_w  = (const float*)d_in[3];
    const float* pre_b  = (const float*)d_in[4];
    const float* c1_w   = (const float*)d_in[5];
    const float* c1_b   = (const float*)d_in[6];
    const float* n1_g   = (const float*)d_in[7];
    const float* n1_b   = (const float*)d_in[8];
    const float* c2_w   = (const float*)d_in[9];
    const float* c2_b   = (const float*)d_in[10];
    const float* n2_g   = (const float*)d_in[11];
    const float* n2_b   = (const float*)d_in[12];
    const float* post_w = (const float*)d_in[13];
    const float* post_b = (const float*)d_in[14];

    int N = in_sizes[0] / 128;
    int E = in_sizes[1] / 2;
    int G = out_size / 40;

    float* p_readout;
    __half *p_hws, *p_h1;
    int *p_cnt, *p_flag;
    cudaGetSymbolAddress((void**)&p_hws,     g_hws);
    cudaGetSymbolAddress((void**)&p_h1,      g_h1);
    cudaGetSymbolAddress((void**)&p_cnt,     g_cnt);
    cudaGetSymbolAddress((void**)&p_flag,    g_scanflag);
    cudaGetSymbolAddress((void**)&p_readout, g_readout);

    static cudaStream_t s1 = nullptr, s2 = nullptr;
    static cudaEvent_t evFork = nullptr, evHist = nullptr, evG1 = nullptr, evCsr = nullptr;
    if (!s1) {
        cudaStreamCreateWithFlags(&s1, cudaStreamNonBlocking);
        cudaStreamCreateWithFlags(&s2, cudaStreamNonBlocking);
        cudaEventCreateWithFlags(&evFork, cudaEventDisableTiming);
        cudaEventCreateWithFlags(&evHist, cudaEventDisableTiming);
        cudaEventCreateWithFlags(&evG1,   cudaEventDisableTiming);
        cudaEventCreateWithFlags(&evCsr,  cudaEventDisableTiming);
    }

    cudaEventRecord(evFork, 0);
    cudaStreamWaitEvent(s1, evFork, 0);
    cudaStreamWaitEvent(s2, evFork, 0);

    // --- s1: weight + x pre-conversion (overlaps s2 CSR chain) ---
    k_cvtw<<<32, 256, 0, s1>>>(pre_w, c1_w, c2_w);
    int total8 = N * 16;   // N*128 halfs / 8 per thread
    k_cvtx<<<(total8 + 255) / 256, 256, 0, s1>>>(x, total8);

    // --- s2: memsets + hist ---
    cudaMemsetAsync(p_cnt, 0, (size_t)N * 4, s2);
    cudaMemsetAsync(p_flag, 0, 128 * 4, s2);
    cudaMemsetAsync(p_readout, 0, (size_t)G * 64 * 4, s2);
    k_hist<<<(E + 1023) / 1024, 256, 0, s2>>>(eidx, E, (long long)N);
    cudaEventRecord(evHist, s2);
    k_scan<<<(N + 1023) / 1024, 256, 0, s2>>>(N);

    // --- s1: fused pre-MLP + layer-1 GEMM (#4 in submit order -> ncu slot) ---
    cudaStreamWaitEvent(s1, evHist, 0);
    k_gemm0<<<(N + 127) / 128, 256, 0, s1>>>(pre_b, p_cnt, p_hws, N);
    cudaEventRecord(evG1, s1);

    // --- s2: fill ---
    k_fill<<<(E + 1023) / 1024, 256, 0, s2>>>(eidx, E, (long long)N);
    cudaEventRecord(evCsr, s2);

    // --- join ---
    cudaStreamWaitEvent(0, evG1, 0);
    cudaStreamWaitEvent(0, evCsr, 0);

    // layer 1 gather -> h1 (fp16)
    k_gather<<<((size_t)N * 8 + 255) / 256, 256>>>(c1_b, n1_g, n1_b, p_h1, N, 0, nullptr);

    // layer 2
    k_gemm_h<<<(N + 127) / 128, 256>>>(p_h1, p_cnt, p_hws, N);
    k_gather<<<((size_t)N * 8 + 255) / 256, 256>>>(c2_b, n2_g, n2_b, nullptr, N, 1, batch);

    // post
    k_post<<<(G + 3) / 4, 256>>>(post_w, post_b, (float*)d_out, G);
}

// round 17
// speedup vs baseline: 1.2258x; 1.0141x over previous
#include <cuda_runtime.h>
#include <cuda_fp16.h>
#include <mma.h>
#include <cstdint>
#include <cstddef>

using namespace nvcuda;

// Problem constants: N=100000, E=1600000, F=128, H=64, C=40, G=2048
#define NMAX 100000
#define EMAX 1600000
#define GMAX 2048

// ---------------- scratch (device globals; no runtime alloc allowed) ----------------
__device__ __align__(128) __half g_xh [NMAX * 128]; // x in fp16
__device__ __align__(128) __half g_hws[NMAX * 64];  // (h @ W) * isq (fp16) per layer
__device__ __align__(128) __half g_h1 [NMAX * 64];  // layer-1 activations (fp16)
__device__ __align__(16)  float  g_deg[NMAX];       // isq
__device__ __align__(128) float  g_readout[GMAX * 64];
__device__ __align__(16)  int    g_cnt[NMAX];       // per-dst degree
__device__ __align__(16)  int    g_ptr[NMAX];       // CSR row starts
__device__ __align__(16)  int    g_cursor[NMAX];    // fill cursors
__device__ __align__(16)  int    g_csr_src[EMAX];   // CSR column (src) indices
__device__ __align__(16)  __half g_w1h[128 * 72];   // pre_w fp16, padded ld=72
__device__ __align__(16)  __half g_w2h[64 * 72];    // c1_w fp16, padded ld=72
__device__ __align__(16)  __half g_w3h[64 * 72];    // c2_w fp16, padded ld=72
__device__ int g_scanflag[128];                     // lookback published aggregates (+1)
__device__ int g_idx32;                             // 1 if indices are int32

// ---------------- fused weight + x fp16 pre-conversion (one kernel) ----------------
__global__ void __launch_bounds__(256) k_cvt(const float* __restrict__ x,
                                             const float* __restrict__ W1,
                                             const float* __restrict__ W2,
                                             const float* __restrict__ W3, int total8) {
    int i = blockIdx.x * blockDim.x + threadIdx.x;
    if (i < 128 * 64) {
        int r = i >> 6, c = i & 63;
        g_w1h[r * 72 + c] = __float2half(W1[i]);
    }
    if (i < 64 * 64) {
        int r = i >> 6, c = i & 63;
        g_w2h[r * 72 + c] = __float2half(W2[i]);
        g_w3h[r * 72 + c] = __float2half(W3[i]);
    }
    if (i < total8) {
        const float4* src = (const float4*)x + (size_t)i * 2;
        float4 f0 = __ldg(&src[0]);
        float4 f1 = __ldg(&src[1]);
        __align__(16) __half2 h[4];
        h[0] = __floats2half2_rn(f0.x, f0.y);
        h[1] = __floats2half2_rn(f0.z, f0.w);
        h[2] = __floats2half2_rn(f1.x, f1.y);
        h[3] = __floats2half2_rn(f1.z, f1.w);
        ((uint4*)g_xh)[i] = *(const uint4*)h;
    }
}

// ---------------- per-block index-dtype detection ----------------
__device__ __forceinline__ int block_detect_idx32(const void* e, int E, long long nlim,
                                                  int* s_flag) {
    if (threadIdx.x == 0) *s_flag = 0;
    __syncthreads();
    int m = E < 64 ? E : 64;
    if ((int)threadIdx.x < m) {
        long long v = ((const long long*)e)[threadIdx.x];
        if (v < 0 || v >= nlim) *s_flag = 1;
    }
    __syncthreads();
    return *s_flag;
}

// ---------------- degree histogram (also zeroes scanflag; scan is stream-after) ------
__global__ void __launch_bounds__(256) k_hist(const void* __restrict__ eidx, int E,
                                              long long nlim) {
    __shared__ int sf;
    int idx32 = block_detect_idx32(eidx, E, nlim, &sf);
    if (blockIdx.x == 0) {
        if (threadIdx.x == 0) g_idx32 = idx32;
        if (threadIdx.x < 128) g_scanflag[threadIdx.x] = 0;
    }
    int base = (blockIdx.x * blockDim.x + threadIdx.x) * 4;
    if (idx32) {
        const int* d = (const int*)eidx + E;
#pragma unroll
        for (int k = 0; k < 4; k++) {
            int e = base + k;
            if (e < E) atomicAdd(&g_cnt[d[e]], 1);
        }
    } else {
        const long long* d = (const long long*)eidx + E;
#pragma unroll
        for (int k = 0; k < 4; k++) {
            int e = base + k;
            if (e < E) atomicAdd(&g_cnt[(int)d[e]], 1);
        }
    }
}

// ---------------- single-pass exclusive scan (lookback) + cursor + isq ----------------
__global__ void __launch_bounds__(256) k_scan(int n) {
    __shared__ int wsum[8];
    __shared__ int red[8];
    __shared__ int s_prefix;
    int bid = blockIdx.x;
    int base = bid * 1024 + threadIdx.x * 4;

    int c0 = 0, c1 = 0, c2 = 0, c3 = 0;
    if (base + 3 < n) {
        int4 c = *(const int4*)&g_cnt[base];
        c0 = c.x; c1 = c.y; c2 = c.z; c3 = c.w;
    } else if (base < n) {
        c0 = g_cnt[base];
        if (base + 1 < n) c1 = g_cnt[base + 1];
        if (base + 2 < n) c2 = g_cnt[base + 2];
    }
    int tot = c0 + c1 + c2 + c3;
    int lane = threadIdx.x & 31, wid = threadIdx.x >> 5;
    int v = tot;
#pragma unroll
    for (int o = 1; o < 32; o <<= 1) {
        int u = __shfl_up_sync(0xffffffffu, v, o);
        if (lane >= o) v += u;
    }
    if (lane == 31) wsum[wid] = v;
    __syncthreads();
    if (threadIdx.x == 0) {
        int s = 0;
        for (int i = 0; i < 8; i++) { int t = wsum[i]; wsum[i] = s; s += t; }
        atomicExch(&g_scanflag[bid], s + 1);
    }
    __syncthreads();

    int part = 0;
    if ((int)threadIdx.x < bid) {
        volatile int* f = &g_scanflag[threadIdx.x];
        int x;
        do { x = *f; } while (x == 0);
        part = x - 1;
    }
#pragma unroll
    for (int o = 16; o; o >>= 1) part += __shfl_xor_sync(0xffffffffu, part, o);
    if (lane == 0) red[wid] = part;
    __syncthreads();
    if (threadIdx.x == 0) {
        int s = 0;
        for (int i = 0; i < 8; i++) s += red[i];
        s_prefix = s;
    }
    __syncthreads();

    int excl = v - tot + wsum[wid] + s_prefix;
    if (base < n) {
        int p0 = excl, p1 = p0 + c0, p2 = p1 + c1, p3 = p2 + c2;
        g_ptr[base] = p0; g_cursor[base] = p0; g_deg[base] = rsqrtf((float)c0 + 1.0f);
        if (base + 1 < n) { g_ptr[base+1] = p1; g_cursor[base+1] = p1; g_deg[base+1] = rsqrtf((float)c1 + 1.0f); }
        if (base + 2 < n) { g_ptr[base+2] = p2; g_cursor[base+2] = p2; g_deg[base+2] = rsqrtf((float)c2 + 1.0f); }
        if (base + 3 < n) { g_ptr[base+3] = p3; g_cursor[base+3] = p3; g_deg[base+3] = rsqrtf((float)c3 + 1.0f); }
    }
}

// ---------------- CSR fill: 8 edges/thread, phase-split (loads -> atomics -> stores) --
__global__ void __launch_bounds__(256) k_fill(const void* __restrict__ eidx, int E,
                                              long long nlim) {
    __shared__ int sf;
    int idx32 = block_detect_idx32(eidx, E, nlim, &sf);
    int base = (blockIdx.x * blockDim.x + threadIdx.x) * 8;

    int srcv[8], dstv[8], pos[8];
    bool val[8];
#pragma unroll
    for (int k = 0; k < 8; k++) {
        int e = base + k;
        val[k] = (e < E);
        srcv[k] = 0; dstv[k] = 0;
        if (val[k]) {
            if (idx32) {
                const int* p = (const int*)eidx;
                srcv[k] = p[e]; dstv[k] = p[E + e];
            } else {
                const long long* p = (const long long*)eidx;
                srcv[k] = (int)p[e]; dstv[k] = (int)p[E + e];
            }
        }
    }
#pragma unroll
    for (int k = 0; k < 8; k++)
        if (val[k]) pos[k] = atomicAdd(&g_cursor[dstv[k]], 1);
#pragma unroll
    for (int k = 0; k < 8; k++)
        if (val[k]) g_csr_src[pos[k]] = srcv[k];
}

// ---------------- fused pre-MLP + layer-1 GEMM: hws = ((xh@W1+b1)@W2)*isq ------------
__global__ void __launch_bounds__(256) k_gemm0(const float* __restrict__ b1,
                                               const int* __restrict__ cnt,
                                               __half* __restrict__ out, int n) {
    __shared__ __align__(16) char sm[46080];
    __half* W1s = (__half*)sm;                       // 128 x 64, ld 72
    __half* W2s = (__half*)(sm + 18432);             // 64 x 64, ld 72
    __half* As  = (__half*)(sm + 27648);             // 128 x 64, ld 72 (warp strips)
    __half* C1  = W1s;                               // aliased after barrier #2

    int tid = threadIdx.x;
    int warpId = tid >> 5, lane = tid & 31;
    int nodeBase = blockIdx.x * 128;

    {
        const uint4* s1 = (const uint4*)g_w1h;
        uint4* d1 = (uint4*)W1s;
        for (int i = tid; i < 1152; i += 256) d1[i] = s1[i];
        const uint4* s2 = (const uint4*)g_w2h;
        uint4* d2 = (uint4*)W2s;
        for (int i = tid; i < 576; i += 256) d2[i] = s2[i];
    }
    __syncthreads();   // barrier #1: W staged

    __half* Aw   = As + warpId * 1152;
    __half* C1w  = C1 + warpId * 1152;
    float*  tmpf = (float*)Aw;

    int srow = tid >> 1;
    int wrow = srow & 15;
    int scol = (tid & 1) * 32;
    int sgn = nodeBase + srow;
    bool sok = (sgn < n);
    const __half* aptr = g_xh + (size_t)sgn * 128 + scol;

    wmma::fragment<wmma::accumulator, 16, 16, 16, float> cf[4];
#pragma unroll
    for (int t = 0; t < 4; t++) wmma::fill_fragment(cf[t], 0.0f);

#pragma unroll
    for (int c = 0; c < 2; c++) {
        __syncwarp();
        {
            uint4 v0, v1, v2, v3;
            if (sok) {
                const uint4* ap = (const uint4*)(aptr + c * 64);
                v0 = __ldg(&ap[0]); v1 = __ldg(&ap[1]);
                v2 = __ldg(&ap[2]); v3 = __ldg(&ap[3]);
            } else {
                v0 = v1 = v2 = v3 = make_uint4(0u, 0u, 0u, 0u);
            }
            uint4* dp = (uint4*)(Aw + wrow * 72 + scol);
            dp[0] = v0; dp[1] = v1; dp[2] = v2; dp[3] = v3;
        }
        __syncwarp();
#pragma unroll
        for (int kk = 0; kk < 64; kk += 16) {
            wmma::fragment<wmma::matrix_a, 16, 16, 16, __half, wmma::row_major> af;
            wmma::load_matrix_sync(af, Aw + kk, 72);
#pragma unroll
            for (int t = 0; t < 4; t++) {
                wmma::fragment<wmma::matrix_b, 16, 16, 16, __half, wmma::row_major> bf;
                wmma::load_matrix_sync(bf, W1s + (c * 64 + kk) * 72 + t * 16, 72);
                wmma::mma_sync(cf[t], af, bf, cf[t]);
            }
        }
    }
    __syncthreads();   // barrier #2: W1s dead -> C1 may overwrite it

    int tr = lane >> 1;
    int tc = (lane & 1) * 8;
#pragma unroll
    for (int t = 0; t < 4; t++) {
        __syncwarp();
        wmma::store_matrix_sync(tmpf, cf[t], 20, wmma::mem_row_major);
        __syncwarp();
        const float* s = tmpf + tr * 20 + tc;
        float4 v0 = *(const float4*)s;
        float4 v1 = *(const float4*)(s + 4);
        float4 ba = *(const float4*)(b1 + t * 16 + tc);
        float4 bb = *(const float4*)(b1 + t * 16 + tc + 4);
        __align__(16) __half2 hs[4];
        hs[0] = __floats2half2_rn(v0.x + ba.x, v0.y + ba.y);
        hs[1] = __floats2half2_rn(v0.z + ba.z, v0.w + ba.w);
        hs[2] = __floats2half2_rn(v1.x + bb.x, v1.y + bb.y);
        hs[3] = __floats2half2_rn(v1.z + bb.z, v1.w + bb.w);
        __syncwarp();
        *(uint4*)(C1w + tr * 72 + t * 16 + tc) = *(const uint4*)hs;
    }
    __syncwarp();

    wmma::fragment<wmma::accumulator, 16, 16, 16, float> cg[4];
#pragma unroll
    for (int t = 0; t < 4; t++) wmma::fill_fragment(cg[t], 0.0f);
#pragma unroll
    for (int kk = 0; kk < 64; kk += 16) {
        wmma::fragment<wmma::matrix_a, 16, 16, 16, __half, wmma::row_major> af;
        wmma::load_matrix_sync(af, C1w + kk, 72);
#pragma unroll
        for (int t = 0; t < 4; t++) {
            wmma::fragment<wmma::matrix_b, 16, 16, 16, __half, wmma::row_major> bf;
            wmma::load_matrix_sync(bf, W2s + kk * 72 + t * 16, 72);
            wmma::mma_sync(cg[t], af, bf, cg[t]);
        }
    }

    int gn = nodeBase + warpId * 16 + tr;
    float siq = (gn < n) ? rsqrtf((float)__ldg(&cnt[gn]) + 1.0f) : 0.f;
#pragma unroll
    for (int t = 0; t < 4; t++) {
        __syncwarp();
        wmma::store_matrix_sync(tmpf, cg[t], 20, wmma::mem_row_major);
        __syncwarp();
        if (gn < n) {
            const float* s = tmpf + tr * 20 + tc;
            float4 v0 = *(const float4*)s;
            float4 v1 = *(const float4*)(s + 4);
            __align__(16) __half2 p[4];
            p[0] = __floats2half2_rn(v0.x * siq, v0.y * siq);
            p[1] = __floats2half2_rn(v0.z * siq, v0.w * siq);
            p[2] = __floats2half2_rn(v1.x * siq, v1.y * siq);
            p[3] = __floats2half2_rn(v1.z * siq, v1.w * siq);
            *(uint4*)(out + (size_t)gn * 64 + t * 16 + tc) = *(const uint4*)p;
        }
    }
}

// ---------------- layer-2 GEMM: hws = (h1 @ W3)*isq, fp16 in/out ----------------
__global__ void __launch_bounds__(256) k_gemm_h(const __half* __restrict__ A,
                                                const int* __restrict__ cnt,
                                                __half* __restrict__ out, int n) {
    __shared__ __align__(16) __half Ws[64 * 72];
    __shared__ __align__(16) __half As[128 * 72];

    int tid = threadIdx.x;
    int warpId = tid >> 5, lane = tid & 31;
    int nodeBase = blockIdx.x * 128;

    {
        const uint4* s3 = (const uint4*)g_w3h;
        uint4* d3 = (uint4*)Ws;
        for (int i = tid; i < 576; i += 256) d3[i] = s3[i];
    }
    __syncthreads();

    __half* Aw = As + warpId * 1152;
    float* tmpf = (float*)Aw;

    int srow = tid >> 1;
    int wrow = srow & 15;
    int scol = (tid & 1) * 32;
    int sgn = nodeBase + srow;
    if (sgn < n) {
        const uint4* ap = (const uint4*)(A + (size_t)sgn * 64 + scol);
        uint4* dp = (uint4*)(Aw + wrow * 72 + scol);
        dp[0] = __ldg(&ap[0]); dp[1] = __ldg(&ap[1]);
        dp[2] = __ldg(&ap[2]); dp[3] = __ldg(&ap[3]);
    } else {
        uint4 z = make_uint4(0u, 0u, 0u, 0u);
        uint4* dp = (uint4*)(Aw + wrow * 72 + scol);
        dp[0] = z; dp[1] = z; dp[2] = z; dp[3] = z;
    }
    __syncwarp();

    wmma::fragment<wmma::accumulator, 16, 16, 16, float> cf[4];
#pragma unroll
    for (int t = 0; t < 4; t++) wmma::fill_fragment(cf[t], 0.0f);
#pragma unroll
    for (int kk = 0; kk < 64; kk += 16) {
        wmma::fragment<wmma::matrix_a, 16, 16, 16, __half, wmma::row_major> af;
        wmma::load_matrix_sync(af, Aw + kk, 72);
#pragma unroll
        for (int t = 0; t < 4; t++) {
            wmma::fragment<wmma::matrix_b, 16, 16, 16, __half, wmma::row_major> bf;
            wmma::load_matrix_sync(bf, Ws + kk * 72 + t * 16, 72);
            wmma::mma_sync(cf[t], af, bf, cf[t]);
        }
    }

    int tr = lane >> 1;
    int tc = (lane & 1) * 8;
    int gn = nodeBase + warpId * 16 + tr;
    float siq = (gn < n) ? rsqrtf((float)__ldg(&cnt[gn]) + 1.0f) : 0.f;
#pragma unroll
    for (int t = 0; t < 4; t++) {
        __syncwarp();
        wmma::store_matrix_sync(tmpf, cf[t], 20, wmma::mem_row_major);
        __syncwarp();
        if (gn < n) {
            const float* s = tmpf + tr * 20 + tc;
            float4 v0 = *(const float4*)s;
            float4 v1 = *(const float4*)(s + 4);
            __align__(16) __half2 p[4];
            p[0] = __floats2half2_rn(v0.x * siq, v0.y * siq);
            p[1] = __floats2half2_rn(v0.z * siq, v0.w * siq);
            p[2] = __floats2half2_rn(v1.x * siq, v1.y * siq);
            p[3] = __floats2half2_rn(v1.z * siq, v1.w * siq);
            *(uint4*)(out + (size_t)gn * 64 + t * 16 + tc) = *(const uint4*)p;
        }
    }
}

// ---------------- fused gather + self + bias + LN + ReLU (+skip+readout) -------------
__global__ void __launch_bounds__(256) k_gather(const float* __restrict__ bias,
                                                const float* __restrict__ lng,
                                                const float* __restrict__ lnb,
                                                __half* __restrict__ outh, int n,
                                                int do_readout,
                                                const void* __restrict__ batch) {
    const unsigned FULL = 0xffffffffu;
    int t = blockIdx.x * blockDim.x + threadIdx.x;
    int node = t >> 3;
    int lane = threadIdx.x & 31;
    int grp = lane >> 3, sub = lane & 7;
    bool ok = (node < n);
    int nodec = ok ? node : (n - 1);

    int start = g_ptr[nodec];
    int cnt   = ok ? g_cnt[nodec] : 0;

    int mmax = cnt;
    mmax = max(mmax, __shfl_xor_sync(FULL, mmax, 8));
    mmax = max(mmax, __shfl_xor_sync(FULL, mmax, 16));

    const uint4* hw4 = (const uint4*)g_hws;
    __half2 acc[4];
    __half2 z = __float2half2_rn(0.f);
#pragma unroll
    for (int k = 0; k < 4; k++) acc[k] = z;

    for (int done = 0; done < mmax; done += 8) {
        int b = 0;
        if (done + sub < cnt) b = __ldg(&g_csr_src[start + done + sub]);
        int lim = cnt - done;
        uint4 v[8];
#pragma unroll
        for (int j = 0; j < 8; j++) {
            int s = __shfl_sync(FULL, b, (grp << 3) + j);
            v[j] = make_uint4(0u, 0u, 0u, 0u);
            if (j < lim) v[j] = __ldg(&hw4[(size_t)s * 8 + sub]);
        }
#pragma unroll
        for (int j = 0; j < 8; j++) {
            const __half2* p = (const __half2*)&v[j];
            acc[0] = __hadd2(acc[0], p[0]);
            acc[1] = __hadd2(acc[1], p[1]);
            acc[2] = __hadd2(acc[2], p[2]);
            acc[3] = __hadd2(acc[3], p[3]);
        }
    }

    uint4 sv = __ldg(&hw4[(size_t)nodec * 8 + sub]);
    const __half2* ps = (const __half2*)&sv;
    float isqn = g_deg[nodec];
    const float4* b4 = (const float4*)bias;
    float4 bl = __ldg(&b4[sub * 2]), bh = __ldg(&b4[sub * 2 + 1]);
    float bb[8] = {bl.x, bl.y, bl.z, bl.w, bh.x, bh.y, bh.z, bh.w};

    float v8[8];
#pragma unroll
    for (int k = 0; k < 4; k++) {
        float2 f  = __half22float2(acc[k]);
        float2 fs = __half22float2(ps[k]);
        v8[2 * k]     = fmaf(isqn, f.x + fs.x, bb[2 * k]);
        v8[2 * k + 1] = fmaf(isqn, f.y + fs.y, bb[2 * k + 1]);
    }

    float sum = 0.f;
#pragma unroll
    for (int i = 0; i < 8; i++) sum += v8[i];
#pragma unroll
    for (int o = 4; o; o >>= 1) sum += __shfl_xor_sync(FULL, sum, o);
    float mu = sum * (1.0f / 64.0f);

    float var = 0.f, d8[8];
#pragma unroll
    for (int i = 0; i < 8; i++) { d8[i] = v8[i] - mu; var += d8[i] * d8[i]; }
#pragma unroll
    for (int o = 4; o; o >>= 1) var += __shfl_xor_sync(FULL, var, o);
    float rstd = rsqrtf(var * (1.0f / 64.0f) + 1e-5f);

    const float4* g4 = (const float4*)lng;
    const float4* l4 = (const float4*)lnb;
    float4 gl = __ldg(&g4[sub * 2]), gh = __ldg(&g4[sub * 2 + 1]);
    float4 ll = __ldg(&l4[sub * 2]), lh = __ldg(&l4[sub * 2 + 1]);
    float gg[8] = {gl.x, gl.y, gl.z, gl.w, gh.x, gh.y, gh.z, gh.w};
    float lb[8] = {ll.x, ll.y, ll.z, ll.w, lh.x, lh.y, lh.z, lh.w};

    float o8[8];
#pragma unroll
    for (int i = 0; i < 8; i++)
        o8[i] = fmaxf(fmaf(d8[i] * rstd, gg[i], lb[i]), 0.f);

    if (!ok) return;
    if (!do_readout) {
        __align__(16) __half2 p[4];
        p[0] = __floats2half2_rn(o8[0], o8[1]);
        p[1] = __floats2half2_rn(o8[2], o8[3]);
        p[2] = __floats2half2_rn(o8[4], o8[5]);
        p[3] = __floats2half2_rn(o8[6], o8[7]);
        *(uint4*)(outh + (size_t)node * 64 + sub * 8) = *(const uint4*)p;
    } else {
        uint4 hv = __ldg((const uint4*)(g_h1 + (size_t)node * 64 + sub * 8));
        const __half2* ph = (const __half2*)&hv;
        float h8[8];
#pragma unroll
        for (int k = 0; k < 4; k++) {
            float2 f = __half22float2(ph[k]);
            h8[2 * k] = f.x; h8[2 * k + 1] = f.y;
        }
        int grpi = g_idx32 ? ((const int*)batch)[node]
                           : (int)((const long long*)batch)[node];
        float4* r4 = (float4*)(g_readout + (size_t)grpi * 64 + sub * 8);
        atomicAdd(&r4[0], make_float4(o8[0] + h8[0], o8[1] + h8[1], o8[2] + h8[2], o8[3] + h8[3]));
        atomicAdd(&r4[1], make_float4(o8[4] + h8[4], o8[5] + h8[5], o8[6] + h8[6], o8[7] + h8[7]));
    }
}

// ---------------- post GEMM: 4 graphs per block ----------------
__global__ void __launch_bounds__(256) k_post(const float* __restrict__ W,
                                              const float* __restrict__ b,
                                              float* __restrict__ out, int G) {
    __shared__ float r[4][64];
    int sgrp = threadIdx.x >> 6;
    int lidx = threadIdx.x & 63;
    int g = blockIdx.x * 4 + sgrp;
    if (g < G) r[sgrp][lidx] = g_readout[(size_t)g * 64 + lidx];
    __syncthreads();
    if (g < G && lidx < 40) {
        float acc = b[lidx];
#pragma unroll
        for (int k = 0; k < 64; k++) acc = fmaf(r[sgrp][k], __ldg(&W[k * 40 + lidx]), acc);
        out[(size_t)g * 40 + lidx] = acc;
    }
}

// ---------------- launch ----------------
extern "C" void kernel_launch(void* const* d_in, const int* in_sizes, int n_in,
                              void* d_out, int out_size) {
    const float* x      = (const float*)d_in[0];
    const void*  eidx   = d_in[1];
    const void*  batch  = d_in[2];
    const float* pre_w  = (const float*)d_in[3];
    const float* pre_b  = (const float*)d_in[4];
    const float* c1_w   = (const float*)d_in[5];
    const float* c1_b   = (const float*)d_in[6];
    const float* n1_g   = (const float*)d_in[7];
    const float* n1_b   = (const float*)d_in[8];
    const float* c2_w   = (const float*)d_in[9];
    const float* c2_b   = (const float*)d_in[10];
    const float* n2_g   = (const float*)d_in[11];
    const float* n2_b   = (const float*)d_in[12];
    const float* post_w = (const float*)d_in[13];
    const float* post_b = (const float*)d_in[14];

    int N = in_sizes[0] / 128;
    int E = in_sizes[1] / 2;
    int G = out_size / 40;

    float* p_readout;
    __half *p_hws, *p_h1;
    int* p_cnt;
    cudaGetSymbolAddress((void**)&p_hws,     g_hws);
    cudaGetSymbolAddress((void**)&p_h1,      g_h1);
    cudaGetSymbolAddress((void**)&p_cnt,     g_cnt);
    cudaGetSymbolAddress((void**)&p_readout, g_readout);

    static cudaStream_t s1 = nullptr, s2 = nullptr;
    static cudaEvent_t evFork = nullptr, evHist = nullptr, evG1 = nullptr, evCsr = nullptr;
    if (!s1) {
        cudaStreamCreateWithFlags(&s1, cudaStreamNonBlocking);
        cudaStreamCreateWithFlags(&s2, cudaStreamNonBlocking);
        cudaEventCreateWithFlags(&evFork, cudaEventDisableTiming);
        cudaEventCreateWithFlags(&evHist, cudaEventDisableTiming);
        cudaEventCreateWithFlags(&evG1,   cudaEventDisableTiming);
        cudaEventCreateWithFlags(&evCsr,  cudaEventDisableTiming);
    }

    cudaEventRecord(evFork, 0);
    cudaStreamWaitEvent(s1, evFork, 0);
    cudaStreamWaitEvent(s2, evFork, 0);

    // --- s1: fused weight + x pre-conversion, readout memset (slack path) ---
    int total8 = N * 16;   // N*128 halfs / 8 per thread
    k_cvt<<<(total8 + 255) / 256, 256, 0, s1>>>(x, pre_w, c1_w, c2_w, total8);
    cudaMemsetAsync(p_readout, 0, (size_t)G * 64 * 4, s1);

    // --- s2: cnt memset + hist (hist also zeroes scanflag) + scan ---
    cudaMemsetAsync(p_cnt, 0, (size_t)N * 4, s2);
    k_hist<<<(E + 1023) / 1024, 256, 0, s2>>>(eidx, E, (long long)N);
    cudaEventRecord(evHist, s2);
    k_scan<<<(N + 1023) / 1024, 256, 0, s2>>>(N);

    // --- s1: fused pre-MLP + layer-1 GEMM (4th kernel -> ncu slot) ---
    cudaStreamWaitEvent(s1, evHist, 0);
    k_gemm0<<<(N + 127) / 128, 256, 0, s1>>>(pre_b, p_cnt, p_hws, N);
    cudaEventRecord(evG1, s1);

    // --- s2: fill (8 edges/thread, phase-split atomics) ---
    k_fill<<<(E + 2047) / 2048, 256, 0, s2>>>(eidx, E, (long long)N);
    cudaEventRecord(evCsr, s2);

    // --- join ---
    cudaStreamWaitEvent(0, evG1, 0);
    cudaStreamWaitEvent(0, evCsr, 0);

    // layer 1 gather -> h1 (fp16)
    k_gather<<<((size_t)N * 8 + 255) / 256, 256>>>(c1_b, n1_g, n1_b, p_h1, N, 0, nullptr);

    // layer 2
    k_gemm_h<<<(N + 127) / 128, 256>>>(p_h1, p_cnt, p_hws, N);
    k_gather<<<((size_t)N * 8 + 255) / 256, 256>>>(c2_b, n2_g, n2_b, nullptr, N, 1, batch);

    // post
    k_post<<<(G + 3) / 4, 256>>>(post_w, post_b, (float*)d_out, G);
}